// round 2
// baseline (speedup 1.0000x reference)
#include <cuda_runtime.h>
#include <math.h>

// Problem constants
#define NN 8192
#define EE 32768
#define EP 40960      // EE + NN self loops
#define DD 768
#define H1H 8
#define CC 768
#define F1 6144       // H1H * CC
#define MM 2048
#define NEG_SLOPE 0.2f

// ---------------- scratch (device globals; no allocation allowed) ----------
__device__ float g_H1[(size_t)NN * F1];      // layer1 pre-agg features h  (192 MB)
__device__ float g_out1[(size_t)NN * F1];    // layer1 aggregated output   (192 MB)
__device__ float g_H2[(size_t)NN * CC];      // layer2 pre-agg features
__device__ float g_out2[(size_t)NN * CC];    // layer2 aggregated output
__device__ float g_asrc1[NN * H1H], g_adst1[NN * H1H];
__device__ unsigned g_m1[NN * H1H];
__device__ float g_den1[NN * H1H];
__device__ float g_score1[(size_t)EP * H1H];
__device__ float g_asrc2[NN], g_adst2[NN];
__device__ unsigned g_m2[NN];
__device__ float g_den2[NN];
__device__ float g_score2[EP];
__device__ int g_src[EP], g_dst[EP], g_midx[MM];
__device__ int g_fe, g_fm;                   // 1 => int64 indices
__device__ float g_cat[(size_t)MM * 2 * CC];
__device__ float g_fc[(size_t)MM * CC];

// ---------------- helpers ----------------
__device__ __forceinline__ unsigned enc_f(float f) {
    unsigned u = __float_as_uint(f);
    return (u & 0x80000000u) ? ~u : (u | 0x80000000u);
}
__device__ __forceinline__ float dec_f(unsigned e) {
    return (e & 0x80000000u) ? __uint_as_float(e ^ 0x80000000u)
                             : __uint_as_float(~e);
}
__device__ __forceinline__ int load_idx(const void* p, long long i, int is64) {
    if (is64) return (int)((const long long*)p)[i];
    return ((const int*)p)[i];
}

// ---------------- index dtype detection ----------------
__global__ void k_detect(const unsigned* e, const unsigned* m) {
    if (threadIdx.x == 0) {
        int fe = 1, fm = 1;
        for (int i = 0; i < 16; i++) if (e[2 * i + 1] != 0u) { fe = 0; break; }
        for (int i = 0; i < 16; i++) if (m[2 * i + 1] != 0u) { fm = 0; break; }
        g_fe = fe; g_fm = fm;
    }
}

__global__ void k_prep(const void* ebuf, const void* mbuf) {
    int i = blockIdx.x * blockDim.x + threadIdx.x;
    int fe = g_fe, fm = g_fm;
    if (i < EP) {
        if (i < EE) {
            g_src[i] = load_idx(ebuf, i, fe);
            g_dst[i] = load_idx(ebuf, (long long)EE + i, fe);
        } else {
            g_src[i] = i - EE;
            g_dst[i] = i - EE;
        }
    }
    if (i < MM) g_midx[i] = load_idx(mbuf, i, fm);
}

// ---------------- SGEMM 128x128x8, 256 threads, 8x8 micro-tile -------------
// C[M,N] = A[M,K] * B[K,N] (+ bias over N).  M%128==0, N%128==0, K%8==0.
__global__ __launch_bounds__(256, 2)
void sgemm128(const float* __restrict__ A, const float* __restrict__ B,
              float* __restrict__ C, int Mn, int Nd, int Kd,
              const float* __restrict__ bias) {
    __shared__ float As[8][128];
    __shared__ float Bs[8][128];
    int tid = threadIdx.x;
    int tx = tid & 15, ty = tid >> 4;
    int row0 = blockIdx.y * 128, col0 = blockIdx.x * 128;

    float acc[8][8];
#pragma unroll
    for (int i = 0; i < 8; i++)
#pragma unroll
        for (int j = 0; j < 8; j++) acc[i][j] = 0.f;

    int arow = tid >> 1;            // 0..127
    int acol = (tid & 1) << 2;      // 0 or 4
    int brow = tid >> 5;            // 0..7
    int bcol = (tid & 31) << 2;     // 0..124

    const float* Aptr = A + (size_t)(row0 + arow) * Kd + acol;
    const float* Bptr = B + (size_t)brow * Nd + col0 + bcol;

    for (int kt = 0; kt < Kd; kt += 8) {
        float4 av = *(const float4*)(Aptr + kt);
        float4 bv = *(const float4*)(Bptr + (size_t)kt * Nd);
        __syncthreads();
        As[acol + 0][arow] = av.x;
        As[acol + 1][arow] = av.y;
        As[acol + 2][arow] = av.z;
        As[acol + 3][arow] = av.w;
        *(float4*)&Bs[brow][bcol] = bv;
        __syncthreads();
#pragma unroll
        for (int kk = 0; kk < 8; kk++) {
            float a[8], b[8];
            *(float4*)(a)     = *(const float4*)&As[kk][ty * 8];
            *(float4*)(a + 4) = *(const float4*)&As[kk][ty * 8 + 4];
            *(float4*)(b)     = *(const float4*)&Bs[kk][tx * 8];
            *(float4*)(b + 4) = *(const float4*)&Bs[kk][tx * 8 + 4];
#pragma unroll
            for (int i = 0; i < 8; i++)
#pragma unroll
                for (int j = 0; j < 8; j++) acc[i][j] += a[i] * b[j];
        }
    }

#pragma unroll
    for (int i = 0; i < 8; i++) {
        size_t r = (size_t)(row0 + ty * 8 + i);
        float* cp = C + r * Nd + col0 + tx * 8;
        if (bias) {
            const float* bp = bias + col0 + tx * 8;
#pragma unroll
            for (int j = 0; j < 8; j++) cp[j] = acc[i][j] + bp[j];
        } else {
#pragma unroll
            for (int j = 0; j < 8; j++) cp[j] = acc[i][j];
        }
    }
}

// ---------------- attention dot products ----------------
// grid = NN, block = 32 * heads; warp w handles head w.
__global__ void k_att(const float* __restrict__ H, const float* __restrict__ av,
                      const float* __restrict__ dv, float* asum, float* dsum,
                      int heads) {
    int n = blockIdx.x;
    int w = threadIdx.x >> 5, lane = threadIdx.x & 31;
    const float* hp = H + ((size_t)n * heads + w) * CC;
    const float* ap = av + w * CC;
    const float* dp = dv + w * CC;
    float s1 = 0.f, s2 = 0.f;
    for (int c = lane; c < CC; c += 32) {
        float v = hp[c];
        s1 += v * ap[c];
        s2 += v * dp[c];
    }
#pragma unroll
    for (int o = 16; o; o >>= 1) {
        s1 += __shfl_xor_sync(0xffffffffu, s1, o);
        s2 += __shfl_xor_sync(0xffffffffu, s2, o);
    }
    if (lane == 0) {
        asum[n * heads + w] = s1;
        dsum[n * heads + w] = s2;
    }
}

// ---------------- edge score + segment max ----------------
__global__ void k_score(int heads, const float* __restrict__ asrc,
                        const float* __restrict__ adst,
                        float* __restrict__ score, unsigned* __restrict__ mbuf) {
    int i = blockIdx.x * blockDim.x + threadIdx.x;
    if (i >= EP * heads) return;
    int e = i / heads, h = i - e * heads;
    int s = g_src[e], d = g_dst[e];
    float v = asrc[s * heads + h] + adst[d * heads + h];
    v = (v > 0.f) ? v : NEG_SLOPE * v;
    score[i] = v;
    atomicMax(&mbuf[d * heads + h], enc_f(v));
}

// ---------------- exp + segment sum ----------------
__global__ void k_expden(int heads, float* __restrict__ score,
                         const unsigned* __restrict__ mbuf,
                         float* __restrict__ den) {
    int i = blockIdx.x * blockDim.x + threadIdx.x;
    if (i >= EP * heads) return;
    int e = i / heads, h = i - e * heads;
    int d = g_dst[e];
    float v = expf(score[i] - dec_f(mbuf[d * heads + h]));
    score[i] = v;
    atomicAdd(&den[d * heads + h], v);
}

// ---------------- weighted scatter-add (one warp per edge-head) ------------
__global__ void k_scatter(int heads, const float* __restrict__ H,
                          const float* __restrict__ score,
                          const float* __restrict__ den,
                          float* __restrict__ out) {
    int gw = (blockIdx.x * blockDim.x + threadIdx.x) >> 5;
    int lane = threadIdx.x & 31;
    if (gw >= EP * heads) return;
    int e = gw / heads, h = gw - e * heads;
    int s = g_src[e], d = g_dst[e];
    float coef = score[gw] / (den[d * heads + h] + 1e-16f);
    const float4* hp = (const float4*)(H + ((size_t)s * heads + h) * CC);
    float* op = out + ((size_t)d * heads + h) * CC;
#pragma unroll
    for (int it = 0; it < 6; it++) {
        int idx = it * 32 + lane;        // float4 index, 192 total
        float4 v = hp[idx];
        v.x *= coef; v.y *= coef; v.z *= coef; v.w *= coef;
        float* a = op + idx * 4;
        asm volatile("red.global.add.v4.f32 [%0], {%1,%2,%3,%4};"
                     :: "l"(a), "f"(v.x), "f"(v.y), "f"(v.z), "f"(v.w)
                     : "memory");
    }
}

// ---------------- bias + ELU ----------------
__global__ void k_elu_bias(float* __restrict__ a, const float* __restrict__ bias,
                           int ncols, size_t total) {
    size_t i = (size_t)blockIdx.x * blockDim.x + threadIdx.x;
    if (i >= total) return;
    float v = a[i] + bias[i % ncols];
    a[i] = (v > 0.f) ? v : expm1f(v);
}

// ---------------- gather + concat (adds b2) ----------------
__global__ void k_cat(const float* __restrict__ out2, const float* __restrict__ b2,
                      const float* __restrict__ x) {
    int i = blockIdx.x * blockDim.x + threadIdx.x;
    if (i >= MM * CC) return;
    int m = i / CC, c = i - m * CC;
    int idx = g_midx[m];
    g_cat[(size_t)m * (2 * CC) + c] = out2[(size_t)idx * CC + c] + b2[c];
    g_cat[(size_t)m * (2 * CC) + CC + c] = x[(size_t)idx * DD + c];
}

// ---------------- classifier [M,768] @ [768,2] + bias ----------------
__global__ void k_cls(const float* __restrict__ fc, const float* __restrict__ w,
                      const float* __restrict__ b, float* __restrict__ out) {
    int m = blockIdx.x, t = threadIdx.x;
    float s0 = 0.f, s1 = 0.f;
    for (int c = t; c < CC; c += 256) {
        float v = fc[(size_t)m * CC + c];
        s0 += v * w[c * 2 + 0];
        s1 += v * w[c * 2 + 1];
    }
    __shared__ float r0[256], r1[256];
    r0[t] = s0; r1[t] = s1;
    __syncthreads();
    for (int o = 128; o; o >>= 1) {
        if (t < o) { r0[t] += r0[t + o]; r1[t] += r1[t + o]; }
        __syncthreads();
    }
    if (t == 0) {
        out[m * 2 + 0] = r0[0] + b[0];
        out[m * 2 + 1] = r1[0] + b[1];
    }
}

// ---------------- launch ----------------
extern "C" void kernel_launch(void* const* d_in, const int* in_sizes, int n_in,
                              void* d_out, int out_size) {
    (void)in_sizes; (void)n_in; (void)out_size;
    const float* x   = (const float*)d_in[0];
    const void*  eix = d_in[1];
    const void*  mix = d_in[2];
    const float* W1  = (const float*)d_in[3];
    const float* as1 = (const float*)d_in[4];
    const float* ad1 = (const float*)d_in[5];
    const float* b1  = (const float*)d_in[6];
    const float* W2  = (const float*)d_in[7];
    const float* as2 = (const float*)d_in[8];
    const float* ad2 = (const float*)d_in[9];
    const float* b2  = (const float*)d_in[10];
    const float* fcw = (const float*)d_in[11];
    const float* fcb = (const float*)d_in[12];
    const float* clw = (const float*)d_in[13];
    const float* clb = (const float*)d_in[14];
    float* out = (float*)d_out;

    // resolve device-global addresses (capture-safe host queries)
    void *pH1, *pOut1, *pH2, *pOut2, *pAs1, *pAd1, *pM1, *pDen1, *pSc1;
    void *pAs2, *pAd2, *pM2, *pDen2, *pSc2, *pCat, *pFc;
    cudaGetSymbolAddress(&pH1, g_H1);
    cudaGetSymbolAddress(&pOut1, g_out1);
    cudaGetSymbolAddress(&pH2, g_H2);
    cudaGetSymbolAddress(&pOut2, g_out2);
    cudaGetSymbolAddress(&pAs1, g_asrc1);
    cudaGetSymbolAddress(&pAd1, g_adst1);
    cudaGetSymbolAddress(&pM1, g_m1);
    cudaGetSymbolAddress(&pDen1, g_den1);
    cudaGetSymbolAddress(&pSc1, g_score1);
    cudaGetSymbolAddress(&pAs2, g_asrc2);
    cudaGetSymbolAddress(&pAd2, g_adst2);
    cudaGetSymbolAddress(&pM2, g_m2);
    cudaGetSymbolAddress(&pDen2, g_den2);
    cudaGetSymbolAddress(&pSc2, g_score2);
    cudaGetSymbolAddress(&pCat, g_cat);
    cudaGetSymbolAddress(&pFc, g_fc);

    // zero the accumulators / softmax state (m encoded: 0 == -inf)
    cudaMemsetAsync(pOut1, 0, (size_t)NN * F1 * 4);
    cudaMemsetAsync(pOut2, 0, (size_t)NN * CC * 4);
    cudaMemsetAsync(pM1, 0, (size_t)NN * H1H * 4);
    cudaMemsetAsync(pDen1, 0, (size_t)NN * H1H * 4);
    cudaMemsetAsync(pM2, 0, (size_t)NN * 4);
    cudaMemsetAsync(pDen2, 0, (size_t)NN * 4);

    k_detect<<<1, 32>>>((const unsigned*)eix, (const unsigned*)mix);
    k_prep<<<(EP + 255) / 256, 256>>>(eix, mix);

    // ---- layer 1 ----
    sgemm128<<<dim3(F1 / 128, NN / 128), 256>>>(x, W1, (float*)pH1, NN, F1, DD, nullptr);
    k_att<<<NN, 32 * H1H>>>((const float*)pH1, as1, ad1, (float*)pAs1, (float*)pAd1, H1H);
    k_score<<<(EP * H1H + 255) / 256, 256>>>(H1H, (const float*)pAs1, (const float*)pAd1,
                                             (float*)pSc1, (unsigned*)pM1);
    k_expden<<<(EP * H1H + 255) / 256, 256>>>(H1H, (float*)pSc1, (const unsigned*)pM1,
                                              (float*)pDen1);
    k_scatter<<<(EP * H1H * 32 + 255) / 256, 256>>>(H1H, (const float*)pH1,
                                                    (const float*)pSc1, (const float*)pDen1,
                                                    (float*)pOut1);
    k_elu_bias<<<(int)(((size_t)NN * F1 + 255) / 256), 256>>>((float*)pOut1, b1, F1,
                                                              (size_t)NN * F1);

    // ---- layer 2 ----
    sgemm128<<<dim3(CC / 128, NN / 128), 256>>>((const float*)pOut1, W2, (float*)pH2,
                                                NN, CC, F1, nullptr);
    k_att<<<NN, 32>>>((const float*)pH2, as2, ad2, (float*)pAs2, (float*)pAd2, 1);
    k_score<<<(EP + 255) / 256, 256>>>(1, (const float*)pAs2, (const float*)pAd2,
                                       (float*)pSc2, (unsigned*)pM2);
    k_expden<<<(EP + 255) / 256, 256>>>(1, (float*)pSc2, (const unsigned*)pM2,
                                        (float*)pDen2);
    k_scatter<<<(EP * 32 + 255) / 256, 256>>>(1, (const float*)pH2, (const float*)pSc2,
                                              (const float*)pDen2, (float*)pOut2);

    // ---- head ----
    k_cat<<<(MM * CC + 255) / 256, 256>>>((const float*)pOut2, b2, x);
    sgemm128<<<dim3(CC / 128, MM / 128), 256>>>((const float*)pCat, fcw, (float*)pFc,
                                                MM, CC, 2 * CC, fcb);
    k_cls<<<MM, 256>>>((const float*)pFc, clw, clb, out);
}

// round 4
// speedup vs baseline: 2.7916x; 2.7916x over previous
#include <cuda_runtime.h>
#include <math.h>
#include <stdint.h>

// Problem constants
#define NN 8192
#define EE 32768
#define EP 40960      // EE + NN self loops
#define DD 768
#define H1H 8
#define CC 768
#define F1 6144       // H1H * CC
#define MM 2048
#define NEG_SLOPE 0.2f

// mma.sync tf32 GEMM tile config
#define BM 128
#define BN 128
#define BK 32
#define GT 256        // threads per GEMM CTA
#define APAD 36       // padded row stride (floats) -> conflict-free frag reads
#define STG 3         // cp.async pipeline stages
#define TILE_F (128 * APAD)

// ---------------- scratch (device globals; no allocation allowed) ----------
__device__ float g_H1[(size_t)NN * F1];
__device__ float g_out1[(size_t)NN * F1];
__device__ float g_H2[(size_t)NN * CC];
__device__ float g_out2[(size_t)NN * CC];
__device__ float g_asrc1[NN * H1H], g_adst1[NN * H1H];
__device__ unsigned g_m1[NN * H1H];
__device__ float g_den1[NN * H1H];
__device__ float g_score1[(size_t)EP * H1H];
__device__ float g_asrc2[NN], g_adst2[NN];
__device__ unsigned g_m2[NN];
__device__ float g_den2[NN];
__device__ float g_score2[EP];
__device__ int g_src[EP], g_dst[EP], g_midx[MM];
__device__ int g_fe, g_fm;
__device__ float g_cat[(size_t)MM * 2 * CC];
__device__ float g_fc[(size_t)MM * CC];
// K-major weights (B operand: Bt[N][K])
__device__ float g_W1T[(size_t)F1 * DD];
__device__ float g_W2T[(size_t)CC * F1];
__device__ float g_fcwT[(size_t)CC * 2 * CC];

// ---------------- helpers ----------------
__device__ __forceinline__ unsigned enc_f(float f) {
    unsigned u = __float_as_uint(f);
    return (u & 0x80000000u) ? ~u : (u | 0x80000000u);
}
__device__ __forceinline__ float dec_f(unsigned e) {
    return (e & 0x80000000u) ? __uint_as_float(e ^ 0x80000000u)
                             : __uint_as_float(~e);
}
__device__ __forceinline__ int load_idx(const void* p, long long i, int is64) {
    if (is64) return (int)((const long long*)p)[i];
    return ((const int*)p)[i];
}
__device__ __forceinline__ uint32_t smem_u32(const void* p) {
    uint32_t a;
    asm("{ .reg .u64 t; cvta.to.shared.u64 t, %1; cvt.u32.u64 %0, t; }"
        : "=r"(a) : "l"(p));
    return a;
}

// ---------------- index dtype detection / prep ----------------
__global__ void k_detect(const unsigned* e, const unsigned* m) {
    if (threadIdx.x == 0) {
        int fe = 1, fm = 1;
        for (int i = 0; i < 16; i++) if (e[2 * i + 1] != 0u) { fe = 0; break; }
        for (int i = 0; i < 16; i++) if (m[2 * i + 1] != 0u) { fm = 0; break; }
        g_fe = fe; g_fm = fm;
    }
}
__global__ void k_prep(const void* ebuf, const void* mbuf) {
    int i = blockIdx.x * blockDim.x + threadIdx.x;
    int fe = g_fe, fm = g_fm;
    if (i < EP) {
        if (i < EE) {
            g_src[i] = load_idx(ebuf, i, fe);
            g_dst[i] = load_idx(ebuf, (long long)EE + i, fe);
        } else {
            g_src[i] = i - EE;
            g_dst[i] = i - EE;
        }
    }
    if (i < MM) g_midx[i] = load_idx(mbuf, i, fm);
}

// ---------------- weight transpose: in[R,C] -> out[C,R] ----------------
__global__ void k_transpose(const float* __restrict__ in, float* __restrict__ out,
                            int R, int C) {
    __shared__ float t[32][33];
    int bx = blockIdx.x * 32, by = blockIdx.y * 32;
    int x = bx + threadIdx.x;
#pragma unroll
    for (int j = 0; j < 32; j += 8) {
        int y = by + threadIdx.y + j;
        t[threadIdx.y + j][threadIdx.x] = in[(size_t)y * C + x];
    }
    __syncthreads();
    int ox = by + threadIdx.x;
#pragma unroll
    for (int j = 0; j < 32; j += 8) {
        int oy = bx + threadIdx.y + j;
        out[(size_t)oy * R + ox] = t[threadIdx.x][threadIdx.y + j];
    }
}

// ---------------- tf32 mma.sync GEMM -----------------------------------
// C[M,N] = A[M,K] @ Bt[N,K]^T (+bias over N). M%128==0, N%128==0, K%32==0.
__global__ __launch_bounds__(GT, 2)
void mma_gemm(const float* __restrict__ A, const float* __restrict__ Bt,
              float* __restrict__ C, int Nd, int Kd,
              const float* __restrict__ bias) {
    extern __shared__ float sm[];   // [STG][A:TILE_F | B:TILE_F]
    int tid = threadIdx.x;
    int wid = tid >> 5, lane = tid & 31;
    int wr = wid & 1, wc = wid >> 1;      // warp 2x4 grid -> 64x32 warptile
    int g = lane >> 2, q = lane & 3;
    int row0 = blockIdx.y * BM, col0 = blockIdx.x * BN;
    const int NIT = Kd / BK;
    uint32_t sbase = smem_u32(sm);

    // stage fill via cp.async: 4 x 16B for A, 4 x 16B for B per thread
    auto issue = [&](int s, int kt) {
        uint32_t as = sbase + (uint32_t)(s * 2 * TILE_F) * 4u;
        uint32_t bs = as + (uint32_t)TILE_F * 4u;
#pragma unroll
        for (int l = 0; l < 4; l++) {
            int p = tid + l * GT;
            int r = p >> 3, c0 = (p & 7) << 2;
            const float* ga = A  + (size_t)(row0 + r) * Kd + kt + c0;
            const float* gb = Bt + (size_t)(col0 + r) * Kd + kt + c0;
            uint32_t da = as + (uint32_t)(r * APAD + c0) * 4u;
            uint32_t db = bs + (uint32_t)(r * APAD + c0) * 4u;
            asm volatile("cp.async.cg.shared.global [%0], [%1], 16;"
                         :: "r"(da), "l"(ga) : "memory");
            asm volatile("cp.async.cg.shared.global [%0], [%1], 16;"
                         :: "r"(db), "l"(gb) : "memory");
        }
        asm volatile("cp.async.commit_group;" ::: "memory");
    };

    float acc[4][4][4];
#pragma unroll
    for (int a = 0; a < 4; a++)
#pragma unroll
        for (int b = 0; b < 4; b++)
#pragma unroll
            for (int c = 0; c < 4; c++) acc[a][b][c] = 0.f;

    issue(0, 0);
    issue(1, BK);

    for (int i = 0; i < NIT; i++) {
        if (i + 2 < NIT) {
            issue((i + 2) % STG, (i + 2) * BK);
            asm volatile("cp.async.wait_group 2;" ::: "memory");
        } else {
            asm volatile("cp.async.wait_group 0;" ::: "memory");
        }
        __syncthreads();

        const float* as = sm + (size_t)(i % STG) * 2 * TILE_F;
        const float* bs = as + TILE_F;
#pragma unroll
        for (int ki = 0; ki < 4; ki++) {
            int kb = ki * 8;
            uint32_t af[4][4], bf[4][2];
#pragma unroll
            for (int mi = 0; mi < 4; mi++) {
                const float* p0 = as + (wr * 64 + mi * 16 + g) * APAD + kb + q;
                af[mi][0] = __float_as_uint(p0[0]);
                af[mi][2] = __float_as_uint(p0[4]);
                af[mi][1] = __float_as_uint(p0[8 * APAD]);
                af[mi][3] = __float_as_uint(p0[8 * APAD + 4]);
            }
#pragma unroll
            for (int ni = 0; ni < 4; ni++) {
                const float* p0 = bs + (wc * 32 + ni * 8 + g) * APAD + kb + q;
                bf[ni][0] = __float_as_uint(p0[0]);
                bf[ni][1] = __float_as_uint(p0[4]);
            }
#pragma unroll
            for (int mi = 0; mi < 4; mi++)
#pragma unroll
                for (int ni = 0; ni < 4; ni++) {
                    asm volatile(
                        "mma.sync.aligned.m16n8k8.row.col.f32.tf32.tf32.f32 "
                        "{%0,%1,%2,%3}, {%4,%5,%6,%7}, {%8,%9}, {%0,%1,%2,%3};"
                        : "+f"(acc[mi][ni][0]), "+f"(acc[mi][ni][1]),
                          "+f"(acc[mi][ni][2]), "+f"(acc[mi][ni][3])
                        : "r"(af[mi][0]), "r"(af[mi][1]),
                          "r"(af[mi][2]), "r"(af[mi][3]),
                          "r"(bf[ni][0]), "r"(bf[ni][1]));
                }
        }
        __syncthreads();
    }

    // epilogue
#pragma unroll
    for (int mi = 0; mi < 4; mi++) {
        int r0 = row0 + wr * 64 + mi * 16 + g;
#pragma unroll
        for (int ni = 0; ni < 4; ni++) {
            int col = col0 + wc * 32 + ni * 8 + q * 2;
            float b0 = 0.f, b1 = 0.f;
            if (bias) { b0 = bias[col]; b1 = bias[col + 1]; }
            float* p0 = C + (size_t)r0 * Nd + col;
            float* p1 = p0 + (size_t)8 * Nd;
            *(float2*)p0 = make_float2(acc[mi][ni][0] + b0, acc[mi][ni][1] + b1);
            *(float2*)p1 = make_float2(acc[mi][ni][2] + b0, acc[mi][ni][3] + b1);
        }
    }
}

// ---------------- attention dot products ----------------
__global__ void k_att(const float* __restrict__ H, const float* __restrict__ av,
                      const float* __restrict__ dv, float* asum, float* dsum,
                      int heads) {
    int n = blockIdx.x;
    int w = threadIdx.x >> 5, lane = threadIdx.x & 31;
    const float* hp = H + ((size_t)n * heads + w) * CC;
    const float* ap = av + w * CC;
    const float* dp = dv + w * CC;
    float s1 = 0.f, s2 = 0.f;
    for (int c = lane; c < CC; c += 32) {
        float v = hp[c];
        s1 += v * ap[c];
        s2 += v * dp[c];
    }
#pragma unroll
    for (int o = 16; o; o >>= 1) {
        s1 += __shfl_xor_sync(0xffffffffu, s1, o);
        s2 += __shfl_xor_sync(0xffffffffu, s2, o);
    }
    if (lane == 0) {
        asum[n * heads + w] = s1;
        dsum[n * heads + w] = s2;
    }
}

// ---------------- edge score + segment max ----------------
__global__ void k_score(int heads, const float* __restrict__ asrc,
                        const float* __restrict__ adst,
                        float* __restrict__ score, unsigned* __restrict__ mbuf) {
    int i = blockIdx.x * blockDim.x + threadIdx.x;
    if (i >= EP * heads) return;
    int e = i / heads, h = i - e * heads;
    int s = g_src[e], d = g_dst[e];
    float v = asrc[s * heads + h] + adst[d * heads + h];
    v = (v > 0.f) ? v : NEG_SLOPE * v;
    score[i] = v;
    atomicMax(&mbuf[d * heads + h], enc_f(v));
}

// ---------------- exp + segment sum ----------------
__global__ void k_expden(int heads, float* __restrict__ score,
                         const unsigned* __restrict__ mbuf,
                         float* __restrict__ den) {
    int i = blockIdx.x * blockDim.x + threadIdx.x;
    if (i >= EP * heads) return;
    int e = i / heads, h = i - e * heads;
    int d = g_dst[e];
    float v = expf(score[i] - dec_f(mbuf[d * heads + h]));
    score[i] = v;
    atomicAdd(&den[d * heads + h], v);
}

// ---------------- weighted scatter-add (one warp per edge-head) ------------
__global__ void k_scatter(int heads, const float* __restrict__ H,
                          const float* __restrict__ score,
                          const float* __restrict__ den,
                          float* __restrict__ out) {
    int gw = (blockIdx.x * blockDim.x + threadIdx.x) >> 5;
    int lane = threadIdx.x & 31;
    if (gw >= EP * heads) return;
    int e = gw / heads, h = gw - e * heads;
    int s = g_src[e], d = g_dst[e];
    float coef = score[gw] / (den[d * heads + h] + 1e-16f);
    const float4* hp = (const float4*)(H + ((size_t)s * heads + h) * CC);
    float* op = out + ((size_t)d * heads + h) * CC;
#pragma unroll
    for (int it = 0; it < 6; it++) {
        int idx = it * 32 + lane;
        float4 v = hp[idx];
        v.x *= coef; v.y *= coef; v.z *= coef; v.w *= coef;
        float* a = op + idx * 4;
        asm volatile("red.global.add.v4.f32 [%0], {%1,%2,%3,%4};"
                     :: "l"(a), "f"(v.x), "f"(v.y), "f"(v.z), "f"(v.w)
                     : "memory");
    }
}

// ---------------- bias + ELU ----------------
__global__ void k_elu_bias(float* __restrict__ a, const float* __restrict__ bias,
                           int ncols, size_t total) {
    size_t i = (size_t)blockIdx.x * blockDim.x + threadIdx.x;
    if (i >= total) return;
    float v = a[i] + bias[i % ncols];
    a[i] = (v > 0.f) ? v : expm1f(v);
}

// ---------------- gather + concat (adds b2) ----------------
__global__ void k_cat(const float* __restrict__ out2, const float* __restrict__ b2,
                      const float* __restrict__ x) {
    int i = blockIdx.x * blockDim.x + threadIdx.x;
    if (i >= MM * CC) return;
    int m = i / CC, c = i - m * CC;
    int idx = g_midx[m];
    g_cat[(size_t)m * (2 * CC) + c] = out2[(size_t)idx * CC + c] + b2[c];
    g_cat[(size_t)m * (2 * CC) + CC + c] = x[(size_t)idx * DD + c];
}

// ---------------- classifier [M,768] @ [768,2] + bias ----------------
__global__ void k_cls(const float* __restrict__ fc, const float* __restrict__ w,
                      const float* __restrict__ b, float* __restrict__ out) {
    int m = blockIdx.x, t = threadIdx.x;
    float s0 = 0.f, s1 = 0.f;
    for (int c = t; c < CC; c += 256) {
        float v = fc[(size_t)m * CC + c];
        s0 += v * w[c * 2 + 0];
        s1 += v * w[c * 2 + 1];
    }
    __shared__ float r0[256], r1[256];
    r0[t] = s0; r1[t] = s1;
    __syncthreads();
    for (int o = 128; o; o >>= 1) {
        if (t < o) { r0[t] += r0[t + o]; r1[t] += r1[t + o]; }
        __syncthreads();
    }
    if (t == 0) {
        out[m * 2 + 0] = r0[0] + b[0];
        out[m * 2 + 1] = r1[0] + b[1];
    }
}

// ---------------- launch ----------------
extern "C" void kernel_launch(void* const* d_in, const int* in_sizes, int n_in,
                              void* d_out, int out_size) {
    (void)in_sizes; (void)n_in; (void)out_size;
    const float* x   = (const float*)d_in[0];
    const void*  eix = d_in[1];
    const void*  mix = d_in[2];
    const float* W1  = (const float*)d_in[3];
    const float* as1 = (const float*)d_in[4];
    const float* ad1 = (const float*)d_in[5];
    const float* b1  = (const float*)d_in[6];
    const float* W2  = (const float*)d_in[7];
    const float* as2 = (const float*)d_in[8];
    const float* ad2 = (const float*)d_in[9];
    const float* b2  = (const float*)d_in[10];
    const float* fcw = (const float*)d_in[11];
    const float* fcb = (const float*)d_in[12];
    const float* clw = (const float*)d_in[13];
    const float* clb = (const float*)d_in[14];
    float* out = (float*)d_out;

    void *pH1, *pOut1, *pH2, *pOut2, *pAs1, *pAd1, *pM1, *pDen1, *pSc1;
    void *pAs2, *pAd2, *pM2, *pDen2, *pSc2, *pCat, *pFc;
    void *pW1T, *pW2T, *pFcwT;
    cudaGetSymbolAddress(&pH1, g_H1);
    cudaGetSymbolAddress(&pOut1, g_out1);
    cudaGetSymbolAddress(&pH2, g_H2);
    cudaGetSymbolAddress(&pOut2, g_out2);
    cudaGetSymbolAddress(&pAs1, g_asrc1);
    cudaGetSymbolAddress(&pAd1, g_adst1);
    cudaGetSymbolAddress(&pM1, g_m1);
    cudaGetSymbolAddress(&pDen1, g_den1);
    cudaGetSymbolAddress(&pSc1, g_score1);
    cudaGetSymbolAddress(&pAs2, g_asrc2);
    cudaGetSymbolAddress(&pAd2, g_adst2);
    cudaGetSymbolAddress(&pM2, g_m2);
    cudaGetSymbolAddress(&pDen2, g_den2);
    cudaGetSymbolAddress(&pSc2, g_score2);
    cudaGetSymbolAddress(&pCat, g_cat);
    cudaGetSymbolAddress(&pFc, g_fc);
    cudaGetSymbolAddress(&pW1T, g_W1T);
    cudaGetSymbolAddress(&pW2T, g_W2T);
    cudaGetSymbolAddress(&pFcwT, g_fcwT);

    const int GEMM_SMEM = STG * 2 * TILE_F * 4;   // 110592 B
    cudaFuncSetAttribute(mma_gemm, cudaFuncAttributeMaxDynamicSharedMemorySize,
                         GEMM_SMEM);

    cudaMemsetAsync(pOut1, 0, (size_t)NN * F1 * 4);
    cudaMemsetAsync(pOut2, 0, (size_t)NN * CC * 4);
    cudaMemsetAsync(pM1, 0, (size_t)NN * H1H * 4);
    cudaMemsetAsync(pDen1, 0, (size_t)NN * H1H * 4);
    cudaMemsetAsync(pM2, 0, (size_t)NN * 4);
    cudaMemsetAsync(pDen2, 0, (size_t)NN * 4);

    k_detect<<<1, 32>>>((const unsigned*)eix, (const unsigned*)mix);
    k_prep<<<(EP + 255) / 256, 256>>>(eix, mix);

    // K-major weights
    k_transpose<<<dim3(F1 / 32, DD / 32), dim3(32, 8)>>>(W1, (float*)pW1T, DD, F1);
    k_transpose<<<dim3(CC / 32, F1 / 32), dim3(32, 8)>>>(W2, (float*)pW2T, F1, CC);
    k_transpose<<<dim3(CC / 32, (2 * CC) / 32), dim3(32, 8)>>>(fcw, (float*)pFcwT,
                                                               2 * CC, CC);

    // ---- layer 1 ----
    mma_gemm<<<dim3(F1 / BN, NN / BM), GT, GEMM_SMEM>>>(
        x, (const float*)pW1T, (float*)pH1, F1, DD, nullptr);
    k_att<<<NN, 32 * H1H>>>((const float*)pH1, as1, ad1, (float*)pAs1, (float*)pAd1, H1H);
    k_score<<<(EP * H1H + 255) / 256, 256>>>(H1H, (const float*)pAs1, (const float*)pAd1,
                                             (float*)pSc1, (unsigned*)pM1);
    k_expden<<<(EP * H1H + 255) / 256, 256>>>(H1H, (float*)pSc1, (const unsigned*)pM1,
                                              (float*)pDen1);
    k_scatter<<<(EP * H1H * 32 + 255) / 256, 256>>>(H1H, (const float*)pH1,
                                                    (const float*)pSc1, (const float*)pDen1,
                                                    (float*)pOut1);
    k_elu_bias<<<(int)(((size_t)NN * F1 + 255) / 256), 256>>>((float*)pOut1, b1, F1,
                                                              (size_t)NN * F1);

    // ---- layer 2 ----
    mma_gemm<<<dim3(CC / BN, NN / BM), GT, GEMM_SMEM>>>(
        (const float*)pOut1, (const float*)pW2T, (float*)pH2, CC, F1, nullptr);
    k_att<<<NN, 32>>>((const float*)pH2, as2, ad2, (float*)pAs2, (float*)pAd2, 1);
    k_score<<<(EP + 255) / 256, 256>>>(1, (const float*)pAs2, (const float*)pAd2,
                                       (float*)pSc2, (unsigned*)pM2);
    k_expden<<<(EP + 255) / 256, 256>>>(1, (float*)pSc2, (const unsigned*)pM2,
                                        (float*)pDen2);
    k_scatter<<<(EP * 32 + 255) / 256, 256>>>(1, (const float*)pH2, (const float*)pSc2,
                                              (const float*)pDen2, (float*)pOut2);

    // ---- head ----
    k_cat<<<(MM * CC + 255) / 256, 256>>>((const float*)pOut2, b2, x);
    mma_gemm<<<dim3(CC / BN, MM / BM), GT, GEMM_SMEM>>>(
        (const float*)pCat, (const float*)pFcwT, (float*)pFc, CC, 2 * CC, fcb);
    k_cls<<<MM, 256>>>((const float*)pFc, clw, clb, out);
}

// round 5
// speedup vs baseline: 3.2890x; 1.1782x over previous
#include <cuda_runtime.h>
#include <math.h>
#include <stdint.h>

// Problem constants
#define NN 8192
#define EE 32768
#define EP 40960      // EE + NN self loops
#define DD 768
#define H1H 8
#define CC 768
#define F1 6144       // H1H * CC
#define MM 2048
#define NEG_SLOPE 0.2f

// mma.sync tf32 GEMM tile config
#define BM 128
#define BN 128
#define BK 32
#define GT 256
#define APAD 36
#define STG 3
#define TILE_F (128 * APAD)

// ---------------- scratch (device globals) ----------------
__device__ float g_H1[(size_t)NN * F1];
__device__ float g_out1[(size_t)NN * F1];
__device__ float g_H2[(size_t)NN * CC];
__device__ float g_out2[(size_t)NN * CC];
__device__ float g_asrc1[NN * H1H], g_adst1[NN * H1H];
__device__ float g_asrc2[NN], g_adst2[NN];
__device__ int g_src[EP], g_dst[EP], g_midx[MM];
__device__ int g_fe, g_fm;
__device__ float g_cat[(size_t)MM * 2 * CC];
__device__ float g_fc[(size_t)MM * CC];
__device__ float g_W1T[(size_t)F1 * DD];
__device__ float g_W2T[(size_t)CC * F1];
__device__ float g_fcwT[(size_t)CC * 2 * CC];
// CSR
__device__ int g_cnt[NN];
__device__ int g_rptr[NN + 1];
__device__ int g_woff[NN];
__device__ int g_csrc[EP];

// ---------------- helpers ----------------
__device__ __forceinline__ int load_idx(const void* p, long long i, int is64) {
    if (is64) return (int)((const long long*)p)[i];
    return ((const int*)p)[i];
}
__device__ __forceinline__ uint32_t smem_u32(const void* p) {
    uint32_t a;
    asm("{ .reg .u64 t; cvta.to.shared.u64 t, %1; cvt.u32.u64 %0, t; }"
        : "=r"(a) : "l"(p));
    return a;
}
__device__ __forceinline__ float tf32r(float x) {
    uint32_t r;
    asm("cvt.rna.tf32.f32 %0, %1;" : "=r"(r) : "f"(x));
    return __uint_as_float(r);
}

// ---------------- index dtype detection / prep ----------------
__global__ void k_detect(const unsigned* e, const unsigned* m) {
    if (threadIdx.x == 0) {
        int fe = 1, fm = 1;
        for (int i = 0; i < 16; i++) if (e[2 * i + 1] != 0u) { fe = 0; break; }
        for (int i = 0; i < 16; i++) if (m[2 * i + 1] != 0u) { fm = 0; break; }
        g_fe = fe; g_fm = fm;
    }
}
__global__ void k_prep(const void* ebuf, const void* mbuf) {
    int i = blockIdx.x * blockDim.x + threadIdx.x;
    int fe = g_fe, fm = g_fm;
    if (i < EP) {
        if (i < EE) {
            g_src[i] = load_idx(ebuf, i, fe);
            g_dst[i] = load_idx(ebuf, (long long)EE + i, fe);
        } else {
            g_src[i] = i - EE;
            g_dst[i] = i - EE;
        }
    }
    if (i < MM) g_midx[i] = load_idx(mbuf, i, fm);
}

// ---------------- CSR build ----------------
__global__ void k_count() {
    int i = blockIdx.x * blockDim.x + threadIdx.x;
    if (i < EP) atomicAdd(&g_cnt[g_dst[i]], 1);
}
__global__ void k_scan() {   // single block, 256 threads x 32 elems
    __shared__ int ps[256];
    int tid = threadIdx.x;
    int base = tid * 32;
    int loc[32];
    int s = 0;
#pragma unroll
    for (int i = 0; i < 32; i++) { loc[i] = s; s += g_cnt[base + i]; }
    ps[tid] = s;
    __syncthreads();
    for (int o = 1; o < 256; o <<= 1) {
        int v = (tid >= o) ? ps[tid - o] : 0;
        __syncthreads();
        ps[tid] += v;
        __syncthreads();
    }
    int off = ps[tid] - s;
#pragma unroll
    for (int i = 0; i < 32; i++) {
        g_rptr[base + i] = off + loc[i];
        g_woff[base + i] = off + loc[i];
    }
    if (tid == 255) g_rptr[NN] = EP;
}
__global__ void k_fill() {
    int i = blockIdx.x * blockDim.x + threadIdx.x;
    if (i >= EP) return;
    int pos = atomicAdd(&g_woff[g_dst[i]], 1);
    g_csrc[pos] = g_src[i];
}

// ---------------- weight transpose ----------------
__global__ void k_transpose(const float* __restrict__ in, float* __restrict__ out,
                            int R, int C) {
    __shared__ float t[32][33];
    int bx = blockIdx.x * 32, by = blockIdx.y * 32;
    int x = bx + threadIdx.x;
#pragma unroll
    for (int j = 0; j < 32; j += 8) {
        int y = by + threadIdx.y + j;
        t[threadIdx.y + j][threadIdx.x] = in[(size_t)y * C + x];
    }
    __syncthreads();
    int ox = by + threadIdx.x;
#pragma unroll
    for (int j = 0; j < 32; j += 8) {
        int oy = bx + threadIdx.y + j;
        out[(size_t)oy * R + ox] = t[threadIdx.x][threadIdx.y + j];
    }
}

// ---------------- tf32 mma.sync GEMM (P3: 3xTF32 precision) ---------------
template <bool P3>
__global__ __launch_bounds__(GT, 2)
void mma_gemm(const float* __restrict__ A, const float* __restrict__ Bt,
              float* __restrict__ C, int Nd, int Kd,
              const float* __restrict__ bias) {
    extern __shared__ float sm[];
    int tid = threadIdx.x;
    int wid = tid >> 5, lane = tid & 31;
    int wr = wid & 1, wc = wid >> 1;
    int g = lane >> 2, q = lane & 3;
    int row0 = blockIdx.y * BM, col0 = blockIdx.x * BN;
    const int NIT = Kd / BK;
    uint32_t sbase = smem_u32(sm);

    auto issue = [&](int s, int kt) {
        uint32_t as = sbase + (uint32_t)(s * 2 * TILE_F) * 4u;
        uint32_t bs = as + (uint32_t)TILE_F * 4u;
#pragma unroll
        for (int l = 0; l < 4; l++) {
            int p = tid + l * GT;
            int r = p >> 3, c0 = (p & 7) << 2;
            const float* ga = A  + (size_t)(row0 + r) * Kd + kt + c0;
            const float* gb = Bt + (size_t)(col0 + r) * Kd + kt + c0;
            uint32_t da = as + (uint32_t)(r * APAD + c0) * 4u;
            uint32_t db = bs + (uint32_t)(r * APAD + c0) * 4u;
            asm volatile("cp.async.cg.shared.global [%0], [%1], 16;"
                         :: "r"(da), "l"(ga) : "memory");
            asm volatile("cp.async.cg.shared.global [%0], [%1], 16;"
                         :: "r"(db), "l"(gb) : "memory");
        }
        asm volatile("cp.async.commit_group;" ::: "memory");
    };

    float acc[4][4][4];
#pragma unroll
    for (int a = 0; a < 4; a++)
#pragma unroll
        for (int b = 0; b < 4; b++)
#pragma unroll
            for (int c = 0; c < 4; c++) acc[a][b][c] = 0.f;

    issue(0, 0);
    issue(1, BK);

    for (int i = 0; i < NIT; i++) {
        if (i + 2 < NIT) {
            issue((i + 2) % STG, (i + 2) * BK);
            asm volatile("cp.async.wait_group 2;" ::: "memory");
        } else {
            asm volatile("cp.async.wait_group 0;" ::: "memory");
        }
        __syncthreads();

        const float* as = sm + (size_t)(i % STG) * 2 * TILE_F;
        const float* bs = as + TILE_F;
#pragma unroll
        for (int ki = 0; ki < 4; ki++) {
            int kb = ki * 8;
            float afv[4][4], bfv[4][2];
#pragma unroll
            for (int mi = 0; mi < 4; mi++) {
                const float* p0 = as + (wr * 64 + mi * 16 + g) * APAD + kb + q;
                afv[mi][0] = p0[0];
                afv[mi][2] = p0[4];
                afv[mi][1] = p0[8 * APAD];
                afv[mi][3] = p0[8 * APAD + 4];
            }
#pragma unroll
            for (int ni = 0; ni < 4; ni++) {
                const float* p0 = bs + (wc * 32 + ni * 8 + g) * APAD + kb + q;
                bfv[ni][0] = p0[0];
                bfv[ni][1] = p0[4];
            }
            if (!P3) {
#pragma unroll
                for (int mi = 0; mi < 4; mi++)
#pragma unroll
                    for (int ni = 0; ni < 4; ni++) {
                        asm volatile(
                            "mma.sync.aligned.m16n8k8.row.col.f32.tf32.tf32.f32 "
                            "{%0,%1,%2,%3}, {%4,%5,%6,%7}, {%8,%9}, {%0,%1,%2,%3};"
                            : "+f"(acc[mi][ni][0]), "+f"(acc[mi][ni][1]),
                              "+f"(acc[mi][ni][2]), "+f"(acc[mi][ni][3])
                            : "r"(__float_as_uint(afv[mi][0])), "r"(__float_as_uint(afv[mi][1])),
                              "r"(__float_as_uint(afv[mi][2])), "r"(__float_as_uint(afv[mi][3])),
                              "r"(__float_as_uint(bfv[ni][0])), "r"(__float_as_uint(bfv[ni][1])));
                    }
            } else {
                float ah[4][4], al[4][4], bh[4][2], bl[4][2];
#pragma unroll
                for (int mi = 0; mi < 4; mi++)
#pragma unroll
                    for (int t = 0; t < 4; t++) {
                        ah[mi][t] = tf32r(afv[mi][t]);
                        al[mi][t] = tf32r(afv[mi][t] - ah[mi][t]);
                    }
#pragma unroll
                for (int ni = 0; ni < 4; ni++)
#pragma unroll
                    for (int t = 0; t < 2; t++) {
                        bh[ni][t] = tf32r(bfv[ni][t]);
                        bl[ni][t] = tf32r(bfv[ni][t] - bh[ni][t]);
                    }
#pragma unroll
                for (int mi = 0; mi < 4; mi++)
#pragma unroll
                    for (int ni = 0; ni < 4; ni++) {
#define MMA1(AA, BB) \
    asm volatile( \
        "mma.sync.aligned.m16n8k8.row.col.f32.tf32.tf32.f32 " \
        "{%0,%1,%2,%3}, {%4,%5,%6,%7}, {%8,%9}, {%0,%1,%2,%3};" \
        : "+f"(acc[mi][ni][0]), "+f"(acc[mi][ni][1]), \
          "+f"(acc[mi][ni][2]), "+f"(acc[mi][ni][3]) \
        : "r"(__float_as_uint(AA[mi][0])), "r"(__float_as_uint(AA[mi][1])), \
          "r"(__float_as_uint(AA[mi][2])), "r"(__float_as_uint(AA[mi][3])), \
          "r"(__float_as_uint(BB[ni][0])), "r"(__float_as_uint(BB[ni][1])))
                        MMA1(al, bh);
                        MMA1(ah, bl);
                        MMA1(ah, bh);
#undef MMA1
                    }
            }
        }
        __syncthreads();
    }

#pragma unroll
    for (int mi = 0; mi < 4; mi++) {
        int r0 = row0 + wr * 64 + mi * 16 + g;
#pragma unroll
        for (int ni = 0; ni < 4; ni++) {
            int col = col0 + wc * 32 + ni * 8 + q * 2;
            float b0 = 0.f, b1 = 0.f;
            if (bias) { b0 = bias[col]; b1 = bias[col + 1]; }
            float* p0 = C + (size_t)r0 * Nd + col;
            float* p1 = p0 + (size_t)8 * Nd;
            *(float2*)p0 = make_float2(acc[mi][ni][0] + b0, acc[mi][ni][1] + b1);
            *(float2*)p1 = make_float2(acc[mi][ni][2] + b0, acc[mi][ni][3] + b1);
        }
    }
}

// ---------------- attention dot products ----------------
__global__ void k_att(const float* __restrict__ H, const float* __restrict__ av,
                      const float* __restrict__ dv, float* asum, float* dsum,
                      int heads) {
    int n = blockIdx.x;
    int w = threadIdx.x >> 5, lane = threadIdx.x & 31;
    const float* hp = H + ((size_t)n * heads + w) * CC;
    const float* ap = av + w * CC;
    const float* dp = dv + w * CC;
    float s1 = 0.f, s2 = 0.f;
    for (int c = lane; c < CC; c += 32) {
        float v = hp[c];
        s1 += v * ap[c];
        s2 += v * dp[c];
    }
#pragma unroll
    for (int o = 16; o; o >>= 1) {
        s1 += __shfl_xor_sync(0xffffffffu, s1, o);
        s2 += __shfl_xor_sync(0xffffffffu, s2, o);
    }
    if (lane == 0) {
        asum[n * heads + w] = s1;
        dsum[n * heads + w] = s2;
    }
}

// ---------------- fused layer-1 aggregation --------------------------------
// block per dst node; softmax over incoming edges (8 heads) + weighted
// gather-accumulate over 6144 channels + bias + ELU.  Plain stores.
#define CH1 64
__global__ __launch_bounds__(256)
void k_agg1(const float* __restrict__ H, const float* __restrict__ asrc,
            const float* __restrict__ adst, const float* __restrict__ bias,
            float* __restrict__ out) {
    int d = blockIdx.x;
    int tid = threadIdx.x, wid = tid >> 5, lane = tid & 31;
    int beg = g_rptr[d], end = g_rptr[d + 1];
    __shared__ float s_m[H1H], s_den[H1H];
    __shared__ float s_coef[CH1 * H1H];
    __shared__ int s_src[CH1];

    // phase 1: per-head max + denom (warp h handles head h)
    {
        int h = wid;
        float adh = adst[d * H1H + h];
        float mx = -1e30f;
        for (int i = beg + lane; i < end; i += 32) {
            float v = asrc[g_csrc[i] * H1H + h] + adh;
            v = (v > 0.f) ? v : NEG_SLOPE * v;
            mx = fmaxf(mx, v);
        }
#pragma unroll
        for (int o = 16; o; o >>= 1) mx = fmaxf(mx, __shfl_xor_sync(~0u, mx, o));
        float sum = 0.f;
        for (int i = beg + lane; i < end; i += 32) {
            float v = asrc[g_csrc[i] * H1H + h] + adh;
            v = (v > 0.f) ? v : NEG_SLOPE * v;
            sum += expf(v - mx);
        }
#pragma unroll
        for (int o = 16; o; o >>= 1) sum += __shfl_xor_sync(~0u, sum, o);
        if (lane == 0) { s_m[h] = mx; s_den[h] = sum + 1e-16f; }
    }
    __syncthreads();

    int hk[24];
#pragma unroll
    for (int k = 0; k < 24; k++) hk[k] = (tid + k * 256) / CC;
    float acc[24];
#pragma unroll
    for (int k = 0; k < 24; k++) acc[k] = 0.f;

    for (int cb = beg; cb < end; cb += CH1) {
        int ch = min(CH1, end - cb);
        for (int i = tid; i < ch * H1H; i += 256) {
            int e = i >> 3, h = i & 7;
            int s = g_csrc[cb + e];
            float v = asrc[s * H1H + h] + adst[d * H1H + h];
            v = (v > 0.f) ? v : NEG_SLOPE * v;
            s_coef[i] = expf(v - s_m[h]) / s_den[h];
            if (h == 0) s_src[e] = s;
        }
        __syncthreads();
        for (int e = 0; e < ch; e++) {
            const float* hp = H + (size_t)s_src[e] * F1;
            const float* cf = &s_coef[e * H1H];
#pragma unroll
            for (int k = 0; k < 24; k++)
                acc[k] += cf[hk[k]] * hp[tid + k * 256];
        }
        __syncthreads();
    }
#pragma unroll
    for (int k = 0; k < 24; k++) {
        int c = tid + k * 256;
        float v = acc[k] + bias[c];
        out[(size_t)d * F1 + c] = (v > 0.f) ? v : expm1f(v);
    }
}

// ---------------- fused layer-2 aggregation (1 head, 768 ch) ---------------
#define CH2 128
__global__ __launch_bounds__(256)
void k_agg2(const float* __restrict__ H, const float* __restrict__ asrc,
            const float* __restrict__ adst, float* __restrict__ out) {
    int d = blockIdx.x;
    int tid = threadIdx.x, wid = tid >> 5, lane = tid & 31;
    int beg = g_rptr[d], end = g_rptr[d + 1];
    __shared__ float s_m, s_den;
    __shared__ float s_coef[CH2];
    __shared__ int s_src[CH2];

    if (wid == 0) {
        float adh = adst[d];
        float mx = -1e30f;
        for (int i = beg + lane; i < end; i += 32) {
            float v = asrc[g_csrc[i]] + adh;
            v = (v > 0.f) ? v : NEG_SLOPE * v;
            mx = fmaxf(mx, v);
        }
#pragma unroll
        for (int o = 16; o; o >>= 1) mx = fmaxf(mx, __shfl_xor_sync(~0u, mx, o));
        float sum = 0.f;
        for (int i = beg + lane; i < end; i += 32) {
            float v = asrc[g_csrc[i]] + adh;
            v = (v > 0.f) ? v : NEG_SLOPE * v;
            sum += expf(v - mx);
        }
#pragma unroll
        for (int o = 16; o; o >>= 1) sum += __shfl_xor_sync(~0u, sum, o);
        if (lane == 0) { s_m = mx; s_den = sum + 1e-16f; }
    }
    __syncthreads();

    float acc[3] = {0.f, 0.f, 0.f};
    for (int cb = beg; cb < end; cb += CH2) {
        int ch = min(CH2, end - cb);
        for (int i = tid; i < ch; i += 256) {
            int s = g_csrc[cb + i];
            float v = asrc[s] + adst[d];
            v = (v > 0.f) ? v : NEG_SLOPE * v;
            s_coef[i] = expf(v - s_m) / s_den;
            s_src[i] = s;
        }
        __syncthreads();
        for (int e = 0; e < ch; e++) {
            const float* hp = H + (size_t)s_src[e] * CC;
            float cf = s_coef[e];
#pragma unroll
            for (int k = 0; k < 3; k++)
                acc[k] += cf * hp[tid + k * 256];
        }
        __syncthreads();
    }
#pragma unroll
    for (int k = 0; k < 3; k++)
        out[(size_t)d * CC + tid + k * 256] = acc[k];
}

// ---------------- gather + concat (adds b2) ----------------
__global__ void k_cat(const float* __restrict__ out2, const float* __restrict__ b2,
                      const float* __restrict__ x) {
    int i = blockIdx.x * blockDim.x + threadIdx.x;
    if (i >= MM * CC) return;
    int m = i / CC, c = i - m * CC;
    int idx = g_midx[m];
    g_cat[(size_t)m * (2 * CC) + c] = out2[(size_t)idx * CC + c] + b2[c];
    g_cat[(size_t)m * (2 * CC) + CC + c] = x[(size_t)idx * DD + c];
}

// ---------------- classifier ----------------
__global__ void k_cls(const float* __restrict__ fc, const float* __restrict__ w,
                      const float* __restrict__ b, float* __restrict__ out) {
    int m = blockIdx.x, t = threadIdx.x;
    float s0 = 0.f, s1 = 0.f;
    for (int c = t; c < CC; c += 256) {
        float v = fc[(size_t)m * CC + c];
        s0 += v * w[c * 2 + 0];
        s1 += v * w[c * 2 + 1];
    }
    __shared__ float r0[256], r1[256];
    r0[t] = s0; r1[t] = s1;
    __syncthreads();
    for (int o = 128; o; o >>= 1) {
        if (t < o) { r0[t] += r0[t + o]; r1[t] += r1[t + o]; }
        __syncthreads();
    }
    if (t == 0) {
        out[m * 2 + 0] = r0[0] + b[0];
        out[m * 2 + 1] = r1[0] + b[1];
    }
}

// ---------------- launch ----------------
extern "C" void kernel_launch(void* const* d_in, const int* in_sizes, int n_in,
                              void* d_out, int out_size) {
    (void)in_sizes; (void)n_in; (void)out_size;
    const float* x   = (const float*)d_in[0];
    const void*  eix = d_in[1];
    const void*  mix = d_in[2];
    const float* W1  = (const float*)d_in[3];
    const float* as1 = (const float*)d_in[4];
    const float* ad1 = (const float*)d_in[5];
    const float* b1  = (const float*)d_in[6];
    const float* W2  = (const float*)d_in[7];
    const float* as2 = (const float*)d_in[8];
    const float* ad2 = (const float*)d_in[9];
    const float* b2  = (const float*)d_in[10];
    const float* fcw = (const float*)d_in[11];
    const float* fcb = (const float*)d_in[12];
    const float* clw = (const float*)d_in[13];
    const float* clb = (const float*)d_in[14];
    float* out = (float*)d_out;

    void *pH1, *pOut1, *pH2, *pOut2, *pAs1, *pAd1, *pAs2, *pAd2;
    void *pCat, *pFc, *pW1T, *pW2T, *pFcwT, *pCnt;
    cudaGetSymbolAddress(&pH1, g_H1);
    cudaGetSymbolAddress(&pOut1, g_out1);
    cudaGetSymbolAddress(&pH2, g_H2);
    cudaGetSymbolAddress(&pOut2, g_out2);
    cudaGetSymbolAddress(&pAs1, g_asrc1);
    cudaGetSymbolAddress(&pAd1, g_adst1);
    cudaGetSymbolAddress(&pAs2, g_asrc2);
    cudaGetSymbolAddress(&pAd2, g_adst2);
    cudaGetSymbolAddress(&pCat, g_cat);
    cudaGetSymbolAddress(&pFc, g_fc);
    cudaGetSymbolAddress(&pW1T, g_W1T);
    cudaGetSymbolAddress(&pW2T, g_W2T);
    cudaGetSymbolAddress(&pFcwT, g_fcwT);
    cudaGetSymbolAddress(&pCnt, g_cnt);

    const int GEMM_SMEM = STG * 2 * TILE_F * 4;
    cudaFuncSetAttribute(mma_gemm<false>, cudaFuncAttributeMaxDynamicSharedMemorySize,
                         GEMM_SMEM);
    cudaFuncSetAttribute(mma_gemm<true>, cudaFuncAttributeMaxDynamicSharedMemorySize,
                         GEMM_SMEM);

    cudaMemsetAsync(pCnt, 0, NN * sizeof(int));
    k_detect<<<1, 32>>>((const unsigned*)eix, (const unsigned*)mix);
    k_prep<<<(EP + 255) / 256, 256>>>(eix, mix);
    k_count<<<(EP + 255) / 256, 256>>>();
    k_scan<<<1, 256>>>();
    k_fill<<<(EP + 255) / 256, 256>>>();

    k_transpose<<<dim3(F1 / 32, DD / 32), dim3(32, 8)>>>(W1, (float*)pW1T, DD, F1);
    k_transpose<<<dim3(CC / 32, F1 / 32), dim3(32, 8)>>>(W2, (float*)pW2T, F1, CC);
    k_transpose<<<dim3(CC / 32, (2 * CC) / 32), dim3(32, 8)>>>(fcw, (float*)pFcwT,
                                                               2 * CC, CC);

    // ---- layer 1 ----
    mma_gemm<false><<<dim3(F1 / BN, NN / BM), GT, GEMM_SMEM>>>(
        x, (const float*)pW1T, (float*)pH1, F1, DD, nullptr);
    k_att<<<NN, 32 * H1H>>>((const float*)pH1, as1, ad1, (float*)pAs1, (float*)pAd1, H1H);
    k_agg1<<<NN, 256>>>((const float*)pH1, (const float*)pAs1, (const float*)pAd1,
                        b1, (float*)pOut1);

    // ---- layer 2 ----
    mma_gemm<false><<<dim3(CC / BN, NN / BM), GT, GEMM_SMEM>>>(
        (const float*)pOut1, (const float*)pW2T, (float*)pH2, CC, F1, nullptr);
    k_att<<<NN, 32>>>((const float*)pH2, as2, ad2, (float*)pAs2, (float*)pAd2, 1);
    k_agg2<<<NN, 256>>>((const float*)pH2, (const float*)pAs2, (const float*)pAd2,
                        (float*)pOut2);

    // ---- head ----
    k_cat<<<(MM * CC + 255) / 256, 256>>>((const float*)pOut2, b2, x);
    mma_gemm<true><<<dim3(CC / BN, MM / BM), GT, GEMM_SMEM>>>(
        (const float*)pCat, (const float*)pFcwT, (float*)pFc, CC, 2 * CC, fcb);
    k_cls<<<MM, 256>>>((const float*)pFc, clw, clb, out);
}

// round 6
// speedup vs baseline: 4.2198x; 1.2830x over previous
#include <cuda_runtime.h>
#include <cuda_fp16.h>
#include <math.h>
#include <stdint.h>

// Problem constants
#define NN 8192
#define EE 32768
#define EP 40960      // EE + NN self loops
#define DD 768
#define H1H 8
#define CC 768
#define F1 6144       // H1H * CC
#define MM 2048
#define NEG_SLOPE 0.2f

// tf32 GEMM (fc head only)
#define BM 128
#define BN 128
#define BK 32
#define GT 256
#define APAD 36
#define STG 3
#define TILE_F (128 * APAD)

// fp16 GEMM
#define HPAD 40                  // halves per smem row (bank-conflict-free)
#define HTILE (128 * HPAD)       // halves per tile

// ---------------- scratch (device globals) ----------------
__device__ __half g_H1h[(size_t)NN * F1];     // layer1 features (fp16)
__device__ __half g_out1h[(size_t)NN * F1];   // layer1 output (fp16, GEMM2 A)
__device__ float  g_H2[(size_t)NN * CC];
__device__ float  g_out2[(size_t)NN * CC];
__device__ __half g_xh[(size_t)NN * DD];      // x in fp16
__device__ float g_asrc1[NN * H1H], g_adst1[NN * H1H];
__device__ float g_asrc2[NN], g_adst2[NN];
__device__ int g_src[EP], g_dst[EP], g_midx[MM];
__device__ int g_fe, g_fm;
__device__ float g_cat[(size_t)MM * 2 * CC];
__device__ float g_fc[(size_t)MM * CC];
__device__ __half g_W1T[(size_t)F1 * DD];     // K-major fp16
__device__ __half g_W2T[(size_t)CC * F1];
__device__ float  g_fcwT[(size_t)CC * 2 * CC];// K-major fp32 (3xTF32 fc)
// CSR
__device__ int g_cnt[NN];
__device__ int g_rptr[NN + 1];
__device__ int g_woff[NN];
__device__ int g_csrc[EP];

// ---------------- helpers ----------------
__device__ __forceinline__ int load_idx(const void* p, long long i, int is64) {
    if (is64) return (int)((const long long*)p)[i];
    return ((const int*)p)[i];
}
__device__ __forceinline__ uint32_t smem_u32(const void* p) {
    uint32_t a;
    asm("{ .reg .u64 t; cvta.to.shared.u64 t, %1; cvt.u32.u64 %0, t; }"
        : "=r"(a) : "l"(p));
    return a;
}
__device__ __forceinline__ float tf32r(float x) {
    uint32_t r;
    asm("cvt.rna.tf32.f32 %0, %1;" : "=r"(r) : "f"(x));
    return __uint_as_float(r);
}
__device__ __forceinline__ float ldval(const float* p) { return *p; }
__device__ __forceinline__ float ldval(const __half* p) { return __half2float(*p); }

// ---------------- index dtype detection / prep ----------------
__global__ void k_detect(const unsigned* e, const unsigned* m) {
    if (threadIdx.x == 0) {
        int fe = 1, fm = 1;
        for (int i = 0; i < 16; i++) if (e[2 * i + 1] != 0u) { fe = 0; break; }
        for (int i = 0; i < 16; i++) if (m[2 * i + 1] != 0u) { fm = 0; break; }
        g_fe = fe; g_fm = fm;
    }
}
__global__ void k_prep(const void* ebuf, const void* mbuf) {
    int i = blockIdx.x * blockDim.x + threadIdx.x;
    int fe = g_fe, fm = g_fm;
    if (i < EP) {
        if (i < EE) {
            g_src[i] = load_idx(ebuf, i, fe);
            g_dst[i] = load_idx(ebuf, (long long)EE + i, fe);
        } else {
            g_src[i] = i - EE;
            g_dst[i] = i - EE;
        }
    }
    if (i < MM) g_midx[i] = load_idx(mbuf, i, fm);
}

// ---------------- CSR build ----------------
__global__ void k_count() {
    int i = blockIdx.x * blockDim.x + threadIdx.x;
    if (i < EP) atomicAdd(&g_cnt[g_dst[i]], 1);
}
__global__ void k_scan() {   // single block, 1024 threads x 8 elems
    __shared__ int ps[1024];
    int tid = threadIdx.x;
    int base = tid * 8;
    int loc[8];
    int s = 0;
#pragma unroll
    for (int i = 0; i < 8; i++) { loc[i] = s; s += g_cnt[base + i]; }
    ps[tid] = s;
    __syncthreads();
    for (int o = 1; o < 1024; o <<= 1) {
        int v = (tid >= o) ? ps[tid - o] : 0;
        __syncthreads();
        ps[tid] += v;
        __syncthreads();
    }
    int off = ps[tid] - s;
#pragma unroll
    for (int i = 0; i < 8; i++) {
        g_rptr[base + i] = off + loc[i];
        g_woff[base + i] = off + loc[i];
    }
    if (tid == 1023) g_rptr[NN] = EP;
}
__global__ void k_fill() {
    int i = blockIdx.x * blockDim.x + threadIdx.x;
    if (i >= EP) return;
    int pos = atomicAdd(&g_woff[g_dst[i]], 1);
    g_csrc[pos] = g_src[i];
}

// ---------------- conversions / transposes ----------------
__global__ void k_cvt_h(const float* __restrict__ in, __half* __restrict__ out,
                        size_t n) {
    size_t i = (size_t)blockIdx.x * blockDim.x + threadIdx.x;
    if (i < n) out[i] = __float2half(in[i]);
}
template <typename OutT>
__global__ void k_transpose(const float* __restrict__ in, OutT* __restrict__ out,
                            int R, int C) {
    __shared__ float t[32][33];
    int bx = blockIdx.x * 32, by = blockIdx.y * 32;
    int x = bx + threadIdx.x;
#pragma unroll
    for (int j = 0; j < 32; j += 8) {
        int y = by + threadIdx.y + j;
        t[threadIdx.y + j][threadIdx.x] = in[(size_t)y * C + x];
    }
    __syncthreads();
    int ox = by + threadIdx.x;
#pragma unroll
    for (int j = 0; j < 32; j += 8) {
        int oy = bx + threadIdx.y + j;
        out[(size_t)oy * R + ox] = (OutT)t[threadIdx.x][threadIdx.y + j];
    }
}

// ---------------- fp16 mma.sync GEMM ---------------------------------------
// C[M,N] = A[M,K] @ Bt[N,K]^T. A, Bt fp16 K-major. OutT = float or __half.
__device__ __forceinline__ void mma16816(float* c, const uint32_t* a,
                                         const uint32_t* b) {
    asm volatile(
        "mma.sync.aligned.m16n8k16.row.col.f32.f16.f16.f32 "
        "{%0,%1,%2,%3}, {%4,%5,%6,%7}, {%8,%9}, {%0,%1,%2,%3};"
        : "+f"(c[0]), "+f"(c[1]), "+f"(c[2]), "+f"(c[3])
        : "r"(a[0]), "r"(a[1]), "r"(a[2]), "r"(a[3]), "r"(b[0]), "r"(b[1]));
}
template <typename OutT>
__global__ __launch_bounds__(GT, 2)
void hgemm(const __half* __restrict__ A, const __half* __restrict__ Bt,
           OutT* __restrict__ C, int Nd, int Kd) {
    extern __shared__ __half hsm[];
    int tid = threadIdx.x;
    int wid = tid >> 5, lane = tid & 31;
    int wr = wid & 1, wc = wid >> 1;
    int g = lane >> 2, q = lane & 3;
    int row0 = blockIdx.y * BM, col0 = blockIdx.x * BN;
    const int NIT = Kd / BK;
    uint32_t sbase = smem_u32(hsm);

    auto issue = [&](int s, int kt) {
        uint32_t as = sbase + (uint32_t)(s * 2 * HTILE) * 2u;
        uint32_t bs = as + (uint32_t)HTILE * 2u;
#pragma unroll
        for (int l = 0; l < 2; l++) {
            int p = tid + l * GT;           // 0..511
            int r = p >> 2, c0 = (p & 3) << 3;   // halves
            const __half* ga = A + (size_t)(row0 + r) * Kd + kt + c0;
            uint32_t da = as + (uint32_t)(r * HPAD + c0) * 2u;
            asm volatile("cp.async.cg.shared.global [%0], [%1], 16;"
                         :: "r"(da), "l"(ga) : "memory");
            const __half* gb = Bt + (size_t)(col0 + r) * Kd + kt + c0;
            uint32_t db = bs + (uint32_t)(r * HPAD + c0) * 2u;
            asm volatile("cp.async.cg.shared.global [%0], [%1], 16;"
                         :: "r"(db), "l"(gb) : "memory");
        }
        asm volatile("cp.async.commit_group;" ::: "memory");
    };

    float acc[4][4][4];
#pragma unroll
    for (int a = 0; a < 4; a++)
#pragma unroll
        for (int b = 0; b < 4; b++)
#pragma unroll
            for (int c = 0; c < 4; c++) acc[a][b][c] = 0.f;

    issue(0, 0);
    issue(1, BK);

    for (int i = 0; i < NIT; i++) {
        if (i + 2 < NIT) {
            issue((i + 2) % STG, (i + 2) * BK);
            asm volatile("cp.async.wait_group 2;" ::: "memory");
        } else {
            asm volatile("cp.async.wait_group 0;" ::: "memory");
        }
        __syncthreads();

        const __half* as = hsm + (size_t)(i % STG) * 2 * HTILE;
        const __half* bs = as + HTILE;
#pragma unroll
        for (int ki = 0; ki < 2; ki++) {
            int kb = ki * 16;
            uint32_t af[4][4], bf[4][2];
#pragma unroll
            for (int mi = 0; mi < 4; mi++) {
                const __half* p0 = as + (wr * 64 + mi * 16 + g) * HPAD + kb + 2 * q;
                af[mi][0] = *(const uint32_t*)(p0);
                af[mi][1] = *(const uint32_t*)(p0 + 8 * HPAD);
                af[mi][2] = *(const uint32_t*)(p0 + 8);
                af[mi][3] = *(const uint32_t*)(p0 + 8 * HPAD + 8);
            }
#pragma unroll
            for (int ni = 0; ni < 4; ni++) {
                const __half* p0 = bs + (wc * 32 + ni * 8 + g) * HPAD + kb + 2 * q;
                bf[ni][0] = *(const uint32_t*)(p0);
                bf[ni][1] = *(const uint32_t*)(p0 + 8);
            }
#pragma unroll
            for (int mi = 0; mi < 4; mi++)
#pragma unroll
                for (int ni = 0; ni < 4; ni++)
                    mma16816(acc[mi][ni], af[mi], bf[ni]);
        }
        __syncthreads();
    }

#pragma unroll
    for (int mi = 0; mi < 4; mi++) {
        int r0 = row0 + wr * 64 + mi * 16 + g;
#pragma unroll
        for (int ni = 0; ni < 4; ni++) {
            int col = col0 + wc * 32 + ni * 8 + q * 2;
            OutT* p0 = C + (size_t)r0 * Nd + col;
            OutT* p1 = p0 + (size_t)8 * Nd;
            p0[0] = (OutT)acc[mi][ni][0]; p0[1] = (OutT)acc[mi][ni][1];
            p1[0] = (OutT)acc[mi][ni][2]; p1[1] = (OutT)acc[mi][ni][3];
        }
    }
}

// ---------------- tf32 3xTF32 GEMM (fc head) -------------------------------
__global__ __launch_bounds__(GT, 2)
void mma_gemm_p3(const float* __restrict__ A, const float* __restrict__ Bt,
                 float* __restrict__ C, int Nd, int Kd,
                 const float* __restrict__ bias) {
    extern __shared__ float sm[];
    int tid = threadIdx.x;
    int wid = tid >> 5, lane = tid & 31;
    int wr = wid & 1, wc = wid >> 1;
    int g = lane >> 2, q = lane & 3;
    int row0 = blockIdx.y * BM, col0 = blockIdx.x * BN;
    const int NIT = Kd / BK;
    uint32_t sbase = smem_u32(sm);

    auto issue = [&](int s, int kt) {
        uint32_t as = sbase + (uint32_t)(s * 2 * TILE_F) * 4u;
        uint32_t bs = as + (uint32_t)TILE_F * 4u;
#pragma unroll
        for (int l = 0; l < 4; l++) {
            int p = tid + l * GT;
            int r = p >> 3, c0 = (p & 7) << 2;
            const float* ga = A  + (size_t)(row0 + r) * Kd + kt + c0;
            const float* gb = Bt + (size_t)(col0 + r) * Kd + kt + c0;
            uint32_t da = as + (uint32_t)(r * APAD + c0) * 4u;
            uint32_t db = bs + (uint32_t)(r * APAD + c0) * 4u;
            asm volatile("cp.async.cg.shared.global [%0], [%1], 16;"
                         :: "r"(da), "l"(ga) : "memory");
            asm volatile("cp.async.cg.shared.global [%0], [%1], 16;"
                         :: "r"(db), "l"(gb) : "memory");
        }
        asm volatile("cp.async.commit_group;" ::: "memory");
    };

    float acc[4][4][4];
#pragma unroll
    for (int a = 0; a < 4; a++)
#pragma unroll
        for (int b = 0; b < 4; b++)
#pragma unroll
            for (int c = 0; c < 4; c++) acc[a][b][c] = 0.f;

    issue(0, 0);
    issue(1, BK);

    for (int i = 0; i < NIT; i++) {
        if (i + 2 < NIT) {
            issue((i + 2) % STG, (i + 2) * BK);
            asm volatile("cp.async.wait_group 2;" ::: "memory");
        } else {
            asm volatile("cp.async.wait_group 0;" ::: "memory");
        }
        __syncthreads();

        const float* as = sm + (size_t)(i % STG) * 2 * TILE_F;
        const float* bs = as + TILE_F;
#pragma unroll
        for (int ki = 0; ki < 4; ki++) {
            int kb = ki * 8;
            float afv[4][4], bfv[4][2];
#pragma unroll
            for (int mi = 0; mi < 4; mi++) {
                const float* p0 = as + (wr * 64 + mi * 16 + g) * APAD + kb + q;
                afv[mi][0] = p0[0];
                afv[mi][2] = p0[4];
                afv[mi][1] = p0[8 * APAD];
                afv[mi][3] = p0[8 * APAD + 4];
            }
#pragma unroll
            for (int ni = 0; ni < 4; ni++) {
                const float* p0 = bs + (wc * 32 + ni * 8 + g) * APAD + kb + q;
                bfv[ni][0] = p0[0];
                bfv[ni][1] = p0[4];
            }
            float ah[4][4], al[4][4], bh[4][2], bl[4][2];
#pragma unroll
            for (int mi = 0; mi < 4; mi++)
#pragma unroll
                for (int t = 0; t < 4; t++) {
                    ah[mi][t] = tf32r(afv[mi][t]);
                    al[mi][t] = tf32r(afv[mi][t] - ah[mi][t]);
                }
#pragma unroll
            for (int ni = 0; ni < 4; ni++)
#pragma unroll
                for (int t = 0; t < 2; t++) {
                    bh[ni][t] = tf32r(bfv[ni][t]);
                    bl[ni][t] = tf32r(bfv[ni][t] - bh[ni][t]);
                }
#pragma unroll
            for (int mi = 0; mi < 4; mi++)
#pragma unroll
                for (int ni = 0; ni < 4; ni++) {
#define MMA1(AA, BB) \
    asm volatile( \
        "mma.sync.aligned.m16n8k8.row.col.f32.tf32.tf32.f32 " \
        "{%0,%1,%2,%3}, {%4,%5,%6,%7}, {%8,%9}, {%0,%1,%2,%3};" \
        : "+f"(acc[mi][ni][0]), "+f"(acc[mi][ni][1]), \
          "+f"(acc[mi][ni][2]), "+f"(acc[mi][ni][3]) \
        : "r"(__float_as_uint(AA[mi][0])), "r"(__float_as_uint(AA[mi][1])), \
          "r"(__float_as_uint(AA[mi][2])), "r"(__float_as_uint(AA[mi][3])), \
          "r"(__float_as_uint(BB[ni][0])), "r"(__float_as_uint(BB[ni][1])))
                    MMA1(al, bh);
                    MMA1(ah, bl);
                    MMA1(ah, bh);
#undef MMA1
                }
        }
        __syncthreads();
    }

#pragma unroll
    for (int mi = 0; mi < 4; mi++) {
        int r0 = row0 + wr * 64 + mi * 16 + g;
#pragma unroll
        for (int ni = 0; ni < 4; ni++) {
            int col = col0 + wc * 32 + ni * 8 + q * 2;
            float b0 = bias[col], b1 = bias[col + 1];
            float* p0 = C + (size_t)r0 * Nd + col;
            float* p1 = p0 + (size_t)8 * Nd;
            *(float2*)p0 = make_float2(acc[mi][ni][0] + b0, acc[mi][ni][1] + b1);
            *(float2*)p1 = make_float2(acc[mi][ni][2] + b0, acc[mi][ni][3] + b1);
        }
    }
}

// ---------------- attention dot products ----------------
template <typename T>
__global__ void k_att(const T* __restrict__ H, const float* __restrict__ av,
                      const float* __restrict__ dv, float* asum, float* dsum,
                      int heads) {
    int n = blockIdx.x;
    int w = threadIdx.x >> 5, lane = threadIdx.x & 31;
    const T* hp = H + ((size_t)n * heads + w) * CC;
    const float* ap = av + w * CC;
    const float* dp = dv + w * CC;
    float s1 = 0.f, s2 = 0.f;
    for (int c = lane; c < CC; c += 32) {
        float v = ldval(hp + c);
        s1 += v * ap[c];
        s2 += v * dp[c];
    }
#pragma unroll
    for (int o = 16; o; o >>= 1) {
        s1 += __shfl_xor_sync(0xffffffffu, s1, o);
        s2 += __shfl_xor_sync(0xffffffffu, s2, o);
    }
    if (lane == 0) {
        asum[n * heads + w] = s1;
        dsum[n * heads + w] = s2;
    }
}

// ---------------- fused layer-1 aggregation (fp16 in/out) ------------------
#define CH1 64
__global__ __launch_bounds__(256)
void k_agg1(const __half* __restrict__ H, const float* __restrict__ asrc,
            const float* __restrict__ adst, const float* __restrict__ bias,
            __half* __restrict__ out) {
    int d = blockIdx.x;
    int tid = threadIdx.x, wid = tid >> 5, lane = tid & 31;
    int beg = g_rptr[d], end = g_rptr[d + 1];
    __shared__ float s_m[H1H], s_den[H1H];
    __shared__ float s_coef[CH1 * H1H];
    __shared__ int s_src[CH1];

    {
        int h = wid;
        float adh = adst[d * H1H + h];
        float mx = -1e30f;
        for (int i = beg + lane; i < end; i += 32) {
            float v = asrc[g_csrc[i] * H1H + h] + adh;
            v = (v > 0.f) ? v : NEG_SLOPE * v;
            mx = fmaxf(mx, v);
        }
#pragma unroll
        for (int o = 16; o; o >>= 1) mx = fmaxf(mx, __shfl_xor_sync(~0u, mx, o));
        float sum = 0.f;
        for (int i = beg + lane; i < end; i += 32) {
            float v = asrc[g_csrc[i] * H1H + h] + adh;
            v = (v > 0.f) ? v : NEG_SLOPE * v;
            sum += expf(v - mx);
        }
#pragma unroll
        for (int o = 16; o; o >>= 1) sum += __shfl_xor_sync(~0u, sum, o);
        if (lane == 0) { s_m[h] = mx; s_den[h] = sum + 1e-16f; }
    }
    __syncthreads();

    int hk[24];
#pragma unroll
    for (int k = 0; k < 24; k++) hk[k] = (tid + k * 256) / CC;
    float acc[24];
#pragma unroll
    for (int k = 0; k < 24; k++) acc[k] = 0.f;

    for (int cb = beg; cb < end; cb += CH1) {
        int ch = min(CH1, end - cb);
        for (int i = tid; i < ch * H1H; i += 256) {
            int e = i >> 3, h = i & 7;
            int s = g_csrc[cb + e];
            float v = asrc[s * H1H + h] + adst[d * H1H + h];
            v = (v > 0.f) ? v : NEG_SLOPE * v;
            s_coef[i] = expf(v - s_m[h]) / s_den[h];
            if (h == 0) s_src[e] = s;
        }
        __syncthreads();
        for (int e = 0; e < ch; e++) {
            const __half* hp = H + (size_t)s_src[e] * F1;
            const float* cf = &s_coef[e * H1H];
#pragma unroll
            for (int k = 0; k < 24; k++)
                acc[k] += cf[hk[k]] * __half2float(hp[tid + k * 256]);
        }
        __syncthreads();
    }
#pragma unroll
    for (int k = 0; k < 24; k++) {
        int c = tid + k * 256;
        float v = acc[k] + bias[c];
        v = (v > 0.f) ? v : expm1f(v);
        out[(size_t)d * F1 + c] = __float2half(v);
    }
}

// ---------------- fused layer-2 aggregation (fp32) ----------------
#define CH2 128
__global__ __launch_bounds__(256)
void k_agg2(const float* __restrict__ H, const float* __restrict__ asrc,
            const float* __restrict__ adst, float* __restrict__ out) {
    int d = blockIdx.x;
    int tid = threadIdx.x, wid = tid >> 5, lane = tid & 31;
    int beg = g_rptr[d], end = g_rptr[d + 1];
    __shared__ float s_m, s_den;
    __shared__ float s_coef[CH2];
    __shared__ int s_src[CH2];

    if (wid == 0) {
        float adh = adst[d];
        float mx = -1e30f;
        for (int i = beg + lane; i < end; i += 32) {
            float v = asrc[g_csrc[i]] + adh;
            v = (v > 0.f) ? v : NEG_SLOPE * v;
            mx = fmaxf(mx, v);
        }
#pragma unroll
        for (int o = 16; o; o >>= 1) mx = fmaxf(mx, __shfl_xor_sync(~0u, mx, o));
        float sum = 0.f;
        for (int i = beg + lane; i < end; i += 32) {
            float v = asrc[g_csrc[i]] + adh;
            v = (v > 0.f) ? v : NEG_SLOPE * v;
            sum += expf(v - mx);
        }
#pragma unroll
        for (int o = 16; o; o >>= 1) sum += __shfl_xor_sync(~0u, sum, o);
        if (lane == 0) { s_m = mx; s_den = sum + 1e-16f; }
    }
    __syncthreads();

    float acc[3] = {0.f, 0.f, 0.f};
    for (int cb = beg; cb < end; cb += CH2) {
        int ch = min(CH2, end - cb);
        for (int i = tid; i < ch; i += 256) {
            int s = g_csrc[cb + i];
            float v = asrc[s] + adst[d];
            v = (v > 0.f) ? v : NEG_SLOPE * v;
            s_coef[i] = expf(v - s_m) / s_den;
            s_src[i] = s;
        }
        __syncthreads();
        for (int e = 0; e < ch; e++) {
            const float* hp = H + (size_t)s_src[e] * CC;
            float cf = s_coef[e];
#pragma unroll
            for (int k = 0; k < 3; k++)
                acc[k] += cf * hp[tid + k * 256];
        }
        __syncthreads();
    }
#pragma unroll
    for (int k = 0; k < 3; k++)
        out[(size_t)d * CC + tid + k * 256] = acc[k];
}

// ---------------- gather + concat (adds b2) ----------------
__global__ void k_cat(const float* __restrict__ out2, const float* __restrict__ b2,
                      const float* __restrict__ x) {
    int i = blockIdx.x * blockDim.x + threadIdx.x;
    if (i >= MM * CC) return;
    int m = i / CC, c = i - m * CC;
    int idx = g_midx[m];
    g_cat[(size_t)m * (2 * CC) + c] = out2[(size_t)idx * CC + c] + b2[c];
    g_cat[(size_t)m * (2 * CC) + CC + c] = x[(size_t)idx * DD + c];
}

// ---------------- classifier ----------------
__global__ void k_cls(const float* __restrict__ fc, const float* __restrict__ w,
                      const float* __restrict__ b, float* __restrict__ out) {
    int m = blockIdx.x, t = threadIdx.x;
    float s0 = 0.f, s1 = 0.f;
    for (int c = t; c < CC; c += 256) {
        float v = fc[(size_t)m * CC + c];
        s0 += v * w[c * 2 + 0];
        s1 += v * w[c * 2 + 1];
    }
    __shared__ float r0[256], r1[256];
    r0[t] = s0; r1[t] = s1;
    __syncthreads();
    for (int o = 128; o; o >>= 1) {
        if (t < o) { r0[t] += r0[t + o]; r1[t] += r1[t + o]; }
        __syncthreads();
    }
    if (t == 0) {
        out[m * 2 + 0] = r0[0] + b[0];
        out[m * 2 + 1] = r1[0] + b[1];
    }
}

// ---------------- launch ----------------
extern "C" void kernel_launch(void* const* d_in, const int* in_sizes, int n_in,
                              void* d_out, int out_size) {
    (void)in_sizes; (void)n_in; (void)out_size;
    const float* x   = (const float*)d_in[0];
    const void*  eix = d_in[1];
    const void*  mix = d_in[2];
    const float* W1  = (const float*)d_in[3];
    const float* as1 = (const float*)d_in[4];
    const float* ad1 = (const float*)d_in[5];
    const float* b1  = (const float*)d_in[6];
    const float* W2  = (const float*)d_in[7];
    const float* as2 = (const float*)d_in[8];
    const float* ad2 = (const float*)d_in[9];
    const float* b2  = (const float*)d_in[10];
    const float* fcw = (const float*)d_in[11];
    const float* fcb = (const float*)d_in[12];
    const float* clw = (const float*)d_in[13];
    const float* clb = (const float*)d_in[14];
    float* out = (float*)d_out;

    void *pH1h, *pOut1h, *pH2, *pOut2, *pXh, *pAs1, *pAd1, *pAs2, *pAd2;
    void *pCat, *pFc, *pW1T, *pW2T, *pFcwT, *pCnt;
    cudaGetSymbolAddress(&pH1h, g_H1h);
    cudaGetSymbolAddress(&pOut1h, g_out1h);
    cudaGetSymbolAddress(&pH2, g_H2);
    cudaGetSymbolAddress(&pOut2, g_out2);
    cudaGetSymbolAddress(&pXh, g_xh);
    cudaGetSymbolAddress(&pAs1, g_asrc1);
    cudaGetSymbolAddress(&pAd1, g_adst1);
    cudaGetSymbolAddress(&pAs2, g_asrc2);
    cudaGetSymbolAddress(&pAd2, g_adst2);
    cudaGetSymbolAddress(&pCat, g_cat);
    cudaGetSymbolAddress(&pFc, g_fc);
    cudaGetSymbolAddress(&pW1T, g_W1T);
    cudaGetSymbolAddress(&pW2T, g_W2T);
    cudaGetSymbolAddress(&pFcwT, g_fcwT);
    cudaGetSymbolAddress(&pCnt, g_cnt);

    const int TF_SMEM = STG * 2 * TILE_F * 4;    // 110592 B
    const int H_SMEM  = STG * 2 * HTILE * 2;     // 61440 B
    cudaFuncSetAttribute(mma_gemm_p3, cudaFuncAttributeMaxDynamicSharedMemorySize,
                         TF_SMEM);
    cudaFuncSetAttribute(hgemm<__half>, cudaFuncAttributeMaxDynamicSharedMemorySize,
                         H_SMEM);
    cudaFuncSetAttribute(hgemm<float>, cudaFuncAttributeMaxDynamicSharedMemorySize,
                         H_SMEM);

    cudaMemsetAsync(pCnt, 0, NN * sizeof(int));
    k_detect<<<1, 32>>>((const unsigned*)eix, (const unsigned*)mix);
    k_prep<<<(EP + 255) / 256, 256>>>(eix, mix);
    k_count<<<(EP + 255) / 256, 256>>>();
    k_scan<<<1, 1024>>>();
    k_fill<<<(EP + 255) / 256, 256>>>();

    k_cvt_h<<<(int)(((size_t)NN * DD + 255) / 256), 256>>>(x, (__half*)pXh,
                                                           (size_t)NN * DD);
    k_transpose<__half><<<dim3(F1 / 32, DD / 32), dim3(32, 8)>>>(
        W1, (__half*)pW1T, DD, F1);
    k_transpose<__half><<<dim3(CC / 32, F1 / 32), dim3(32, 8)>>>(
        W2, (__half*)pW2T, F1, CC);
    k_transpose<float><<<dim3(CC / 32, (2 * CC) / 32), dim3(32, 8)>>>(
        fcw, (float*)pFcwT, 2 * CC, CC);

    // ---- layer 1 ----
    hgemm<__half><<<dim3(F1 / BN, NN / BM), GT, H_SMEM>>>(
        (const __half*)pXh, (const __half*)pW1T, (__half*)pH1h, F1, DD);
    k_att<__half><<<NN, 32 * H1H>>>((const __half*)pH1h, as1, ad1,
                                    (float*)pAs1, (float*)pAd1, H1H);
    k_agg1<<<NN, 256>>>((const __half*)pH1h, (const float*)pAs1, (const float*)pAd1,
                        b1, (__half*)pOut1h);

    // ---- layer 2 ----
    hgemm<float><<<dim3(CC / BN, NN / BM), GT, H_SMEM>>>(
        (const __half*)pOut1h, (const __half*)pW2T, (float*)pH2, CC, F1);
    k_att<float><<<NN, 32>>>((const float*)pH2, as2, ad2,
                             (float*)pAs2, (float*)pAd2, 1);
    k_agg2<<<NN, 256>>>((const float*)pH2, (const float*)pAs2, (const float*)pAd2,
                        (float*)pOut2);

    // ---- head ----
    k_cat<<<(MM * CC + 255) / 256, 256>>>((const float*)pOut2, b2, x);
    mma_gemm_p3<<<dim3(CC / BN, MM / BM), GT, TF_SMEM>>>(
        (const float*)pCat, (const float*)pFcwT, (float*)pFc, CC, 2 * CC, fcb);
    k_cls<<<MM, 256>>>((const float*)pFc, clw, clb, out);
}

// round 7
// speedup vs baseline: 4.9798x; 1.1801x over previous
#include <cuda_runtime.h>
#include <cuda_fp16.h>
#include <math.h>
#include <stdint.h>

// Problem constants
#define NN 8192
#define EE 32768
#define EP 40960      // EE + NN self loops
#define DD 768
#define H1H 8
#define CC 768
#define F1 6144       // H1H * CC
#define MM 2048
#define NEG_SLOPE 0.2f

// tf32 GEMM (fc head only)
#define BM 128
#define BN 128
#define BK 32
#define GT 256
#define APAD 36
#define STG 3
#define TILE_F (128 * APAD)

// fp16 GEMM
#define HPAD 40                  // halves per smem row (conflict-free for LDSM)
#define HTILE (128 * HPAD)

// ---------------- scratch (device globals) ----------------
__device__ __half g_H1h[(size_t)NN * F1];
__device__ __half g_out1h[(size_t)NN * F1];
__device__ float  g_H2[(size_t)NN * CC];
__device__ float  g_out2[(size_t)NN * CC];
__device__ __half g_xh[(size_t)NN * DD];
__device__ float g_asrc1[NN * H1H], g_adst1[NN * H1H];
__device__ float g_asrc2[NN], g_adst2[NN];
__device__ int g_src[EP], g_dst[EP], g_midx[MM];
__device__ int g_fe, g_fm;
__device__ float g_cat[(size_t)MM * 2 * CC];
__device__ float g_fc[(size_t)MM * CC];
__device__ __half g_W1T[(size_t)F1 * DD];
__device__ __half g_W2T[(size_t)CC * F1];
__device__ float  g_fcwT[(size_t)CC * 2 * CC];
// CSR
__device__ int g_cnt[NN];
__device__ int g_rptr[NN + 1];
__device__ int g_woff[NN];
__device__ int g_csrc[EP];

// ---------------- helpers ----------------
__device__ __forceinline__ int load_idx(const void* p, long long i, int is64) {
    if (is64) return (int)((const long long*)p)[i];
    return ((const int*)p)[i];
}
__device__ __forceinline__ uint32_t smem_u32(const void* p) {
    uint32_t a;
    asm("{ .reg .u64 t; cvta.to.shared.u64 t, %1; cvt.u32.u64 %0, t; }"
        : "=r"(a) : "l"(p));
    return a;
}
__device__ __forceinline__ float tf32r(float x) {
    uint32_t r;
    asm("cvt.rna.tf32.f32 %0, %1;" : "=r"(r) : "f"(x));
    return __uint_as_float(r);
}
__device__ __forceinline__ float ldval(const float* p) { return *p; }
__device__ __forceinline__ float ldval(const __half* p) { return __half2float(*p); }

#define LDSM4(r0, r1, r2, r3, addr) \
    asm volatile("ldmatrix.sync.aligned.m8n8.x4.shared.b16 {%0,%1,%2,%3}, [%4];" \
                 : "=r"(r0), "=r"(r1), "=r"(r2), "=r"(r3) : "r"(addr))

// ---------------- index dtype detection / prep ----------------
__global__ void k_detect(const unsigned* e, const unsigned* m) {
    if (threadIdx.x == 0) {
        int fe = 1, fm = 1;
        for (int i = 0; i < 16; i++) if (e[2 * i + 1] != 0u) { fe = 0; break; }
        for (int i = 0; i < 16; i++) if (m[2 * i + 1] != 0u) { fm = 0; break; }
        g_fe = fe; g_fm = fm;
    }
}
__global__ void k_prep(const void* ebuf, const void* mbuf) {
    int i = blockIdx.x * blockDim.x + threadIdx.x;
    int fe = g_fe, fm = g_fm;
    if (i < EP) {
        if (i < EE) {
            g_src[i] = load_idx(ebuf, i, fe);
            g_dst[i] = load_idx(ebuf, (long long)EE + i, fe);
        } else {
            g_src[i] = i - EE;
            g_dst[i] = i - EE;
        }
    }
    if (i < MM) g_midx[i] = load_idx(mbuf, i, fm);
}

// ---------------- CSR build ----------------
__global__ void k_count() {
    int i = blockIdx.x * blockDim.x + threadIdx.x;
    if (i < EP) atomicAdd(&g_cnt[g_dst[i]], 1);
}
__global__ void k_scan() {   // 1024 threads x 8, warp-shuffle scan
    __shared__ int wsum[32];
    int tid = threadIdx.x;
    int lane = tid & 31, w = tid >> 5;
    int base = tid * 8;
    int loc[8];
    int s = 0;
#pragma unroll
    for (int i = 0; i < 8; i++) { loc[i] = s; s += g_cnt[base + i]; }
    int inc = s;
#pragma unroll
    for (int o = 1; o < 32; o <<= 1) {
        int v = __shfl_up_sync(~0u, inc, o);
        if (lane >= o) inc += v;
    }
    if (lane == 31) wsum[w] = inc;
    __syncthreads();
    if (w == 0) {
        int v = wsum[lane];
#pragma unroll
        for (int o = 1; o < 32; o <<= 1) {
            int t = __shfl_up_sync(~0u, v, o);
            if (lane >= o) v += t;
        }
        wsum[lane] = v;
    }
    __syncthreads();
    int off = inc - s + (w ? wsum[w - 1] : 0);
#pragma unroll
    for (int i = 0; i < 8; i++) {
        g_rptr[base + i] = off + loc[i];
        g_woff[base + i] = off + loc[i];
    }
    if (tid == 1023) g_rptr[NN] = EP;
}
__global__ void k_fill() {
    int i = blockIdx.x * blockDim.x + threadIdx.x;
    if (i >= EP) return;
    int pos = atomicAdd(&g_woff[g_dst[i]], 1);
    g_csrc[pos] = g_src[i];
}

// ---------------- conversions / transposes ----------------
__global__ void k_cvt_h(const float* __restrict__ in, __half* __restrict__ out,
                        size_t n) {
    size_t i = (size_t)blockIdx.x * blockDim.x + threadIdx.x;
    if (i < n) out[i] = __float2half(in[i]);
}
template <typename OutT>
__global__ void k_transpose(const float* __restrict__ in, OutT* __restrict__ out,
                            int R, int C) {
    __shared__ float t[32][33];
    int bx = blockIdx.x * 32, by = blockIdx.y * 32;
    int x = bx + threadIdx.x;
#pragma unroll
    for (int j = 0; j < 32; j += 8) {
        int y = by + threadIdx.y + j;
        t[threadIdx.y + j][threadIdx.x] = in[(size_t)y * C + x];
    }
    __syncthreads();
    int ox = by + threadIdx.x;
#pragma unroll
    for (int j = 0; j < 32; j += 8) {
        int oy = bx + threadIdx.y + j;
        out[(size_t)oy * R + ox] = (OutT)t[threadIdx.x][threadIdx.y + j];
    }
}

// ---------------- fp16 mma.sync GEMM with ldmatrix -------------------------
__device__ __forceinline__ void mma16816(float* c, const uint32_t* a,
                                         const uint32_t* b) {
    asm volatile(
        "mma.sync.aligned.m16n8k16.row.col.f32.f16.f16.f32 "
        "{%0,%1,%2,%3}, {%4,%5,%6,%7}, {%8,%9}, {%0,%1,%2,%3};"
        : "+f"(c[0]), "+f"(c[1]), "+f"(c[2]), "+f"(c[3])
        : "r"(a[0]), "r"(a[1]), "r"(a[2]), "r"(a[3]), "r"(b[0]), "r"(b[1]));
}
template <typename OutT>
__global__ __launch_bounds__(GT, 2)
void hgemm(const __half* __restrict__ A, const __half* __restrict__ Bt,
           OutT* __restrict__ C, int Nd, int Kd) {
    extern __shared__ __half hsm[];
    int tid = threadIdx.x;
    int wid = tid >> 5, lane = tid & 31;
    int wr = wid & 1, wc = wid >> 1;
    int g = lane >> 2, q = lane & 3;
    int row0 = blockIdx.y * BM, col0 = blockIdx.x * BN;
    const int NIT = Kd / BK;
    uint32_t sbase = smem_u32(hsm);

    // ldmatrix per-lane base offsets (bytes), relative to stage A/B base
    uint32_t a_off = (uint32_t)(((wr * 64 + (lane & 15)) * HPAD
                                 + ((lane & 16) ? 8 : 0)) * 2);
    uint32_t b_off = (uint32_t)(((wc * 32 + (lane & 7) + ((lane & 16) ? 8 : 0)) * HPAD
                                 + ((lane & 8) ? 8 : 0)) * 2);

    auto issue = [&](int s, int kt) {
        uint32_t as = sbase + (uint32_t)(s * 2 * HTILE) * 2u;
        uint32_t bs = as + (uint32_t)HTILE * 2u;
#pragma unroll
        for (int l = 0; l < 2; l++) {
            int p = tid + l * GT;
            int r = p >> 2, c0 = (p & 3) << 3;
            const __half* ga = A + (size_t)(row0 + r) * Kd + kt + c0;
            uint32_t da = as + (uint32_t)(r * HPAD + c0) * 2u;
            asm volatile("cp.async.cg.shared.global [%0], [%1], 16;"
                         :: "r"(da), "l"(ga) : "memory");
            const __half* gb = Bt + (size_t)(col0 + r) * Kd + kt + c0;
            uint32_t db = bs + (uint32_t)(r * HPAD + c0) * 2u;
            asm volatile("cp.async.cg.shared.global [%0], [%1], 16;"
                         :: "r"(db), "l"(gb) : "memory");
        }
        asm volatile("cp.async.commit_group;" ::: "memory");
    };

    float acc[4][4][4];
#pragma unroll
    for (int a = 0; a < 4; a++)
#pragma unroll
        for (int b = 0; b < 4; b++)
#pragma unroll
            for (int c = 0; c < 4; c++) acc[a][b][c] = 0.f;

    issue(0, 0);
    issue(1, BK);

    for (int i = 0; i < NIT; i++) {
        if (i + 2 < NIT) {
            issue((i + 2) % STG, (i + 2) * BK);
            asm volatile("cp.async.wait_group 2;" ::: "memory");
        } else {
            asm volatile("cp.async.wait_group 0;" ::: "memory");
        }
        __syncthreads();

        uint32_t as = sbase + (uint32_t)((i % STG) * 2 * HTILE) * 2u;
        uint32_t bs = as + (uint32_t)HTILE * 2u;
#pragma unroll
        for (int ki = 0; ki < 2; ki++) {
            uint32_t kb2 = (uint32_t)(ki * 16 * 2);   // byte offset of k-slice
            uint32_t af[4][4], bf[4][2];
#pragma unroll
            for (int mi = 0; mi < 4; mi++) {
                uint32_t addr = as + a_off + (uint32_t)(mi * 16 * HPAD * 2) + kb2;
                LDSM4(af[mi][0], af[mi][1], af[mi][2], af[mi][3], addr);
            }
#pragma unroll
            for (int np = 0; np < 2; np++) {
                uint32_t addr = bs + b_off + (uint32_t)(np * 16 * HPAD * 2) + kb2;
                LDSM4(bf[2 * np][0], bf[2 * np][1],
                      bf[2 * np + 1][0], bf[2 * np + 1][1], addr);
            }
#pragma unroll
            for (int mi = 0; mi < 4; mi++)
#pragma unroll
                for (int ni = 0; ni < 4; ni++)
                    mma16816(acc[mi][ni], af[mi], bf[ni]);
        }
        __syncthreads();
    }

#pragma unroll
    for (int mi = 0; mi < 4; mi++) {
        int r0 = row0 + wr * 64 + mi * 16 + g;
#pragma unroll
        for (int ni = 0; ni < 4; ni++) {
            int col = col0 + wc * 32 + ni * 8 + q * 2;
            OutT* p0 = C + (size_t)r0 * Nd + col;
            OutT* p1 = p0 + (size_t)8 * Nd;
            if (sizeof(OutT) == 2) {
                *(__half2*)p0 = __floats2half2_rn(acc[mi][ni][0], acc[mi][ni][1]);
                *(__half2*)p1 = __floats2half2_rn(acc[mi][ni][2], acc[mi][ni][3]);
            } else {
                p0[0] = (OutT)acc[mi][ni][0]; p0[1] = (OutT)acc[mi][ni][1];
                p1[0] = (OutT)acc[mi][ni][2]; p1[1] = (OutT)acc[mi][ni][3];
            }
        }
    }
}

// ---------------- tf32 3xTF32 GEMM (fc head) -------------------------------
__global__ __launch_bounds__(GT, 2)
void mma_gemm_p3(const float* __restrict__ A, const float* __restrict__ Bt,
                 float* __restrict__ C, int Nd, int Kd,
                 const float* __restrict__ bias) {
    extern __shared__ float sm[];
    int tid = threadIdx.x;
    int wid = tid >> 5, lane = tid & 31;
    int wr = wid & 1, wc = wid >> 1;
    int g = lane >> 2, q = lane & 3;
    int row0 = blockIdx.y * BM, col0 = blockIdx.x * BN;
    const int NIT = Kd / BK;
    uint32_t sbase = smem_u32(sm);

    auto issue = [&](int s, int kt) {
        uint32_t as = sbase + (uint32_t)(s * 2 * TILE_F) * 4u;
        uint32_t bs = as + (uint32_t)TILE_F * 4u;
#pragma unroll
        for (int l = 0; l < 4; l++) {
            int p = tid + l * GT;
            int r = p >> 3, c0 = (p & 7) << 2;
            const float* ga = A  + (size_t)(row0 + r) * Kd + kt + c0;
            const float* gb = Bt + (size_t)(col0 + r) * Kd + kt + c0;
            uint32_t da = as + (uint32_t)(r * APAD + c0) * 4u;
            uint32_t db = bs + (uint32_t)(r * APAD + c0) * 4u;
            asm volatile("cp.async.cg.shared.global [%0], [%1], 16;"
                         :: "r"(da), "l"(ga) : "memory");
            asm volatile("cp.async.cg.shared.global [%0], [%1], 16;"
                         :: "r"(db), "l"(gb) : "memory");
        }
        asm volatile("cp.async.commit_group;" ::: "memory");
    };

    float acc[4][4][4];
#pragma unroll
    for (int a = 0; a < 4; a++)
#pragma unroll
        for (int b = 0; b < 4; b++)
#pragma unroll
            for (int c = 0; c < 4; c++) acc[a][b][c] = 0.f;

    issue(0, 0);
    issue(1, BK);

    for (int i = 0; i < NIT; i++) {
        if (i + 2 < NIT) {
            issue((i + 2) % STG, (i + 2) * BK);
            asm volatile("cp.async.wait_group 2;" ::: "memory");
        } else {
            asm volatile("cp.async.wait_group 0;" ::: "memory");
        }
        __syncthreads();

        const float* as = sm + (size_t)(i % STG) * 2 * TILE_F;
        const float* bs = as + TILE_F;
#pragma unroll
        for (int ki = 0; ki < 4; ki++) {
            int kb = ki * 8;
            float afv[4][4], bfv[4][2];
#pragma unroll
            for (int mi = 0; mi < 4; mi++) {
                const float* p0 = as + (wr * 64 + mi * 16 + g) * APAD + kb + q;
                afv[mi][0] = p0[0];
                afv[mi][2] = p0[4];
                afv[mi][1] = p0[8 * APAD];
                afv[mi][3] = p0[8 * APAD + 4];
            }
#pragma unroll
            for (int ni = 0; ni < 4; ni++) {
                const float* p0 = bs + (wc * 32 + ni * 8 + g) * APAD + kb + q;
                bfv[ni][0] = p0[0];
                bfv[ni][1] = p0[4];
            }
            float ah[4][4], al[4][4], bh[4][2], bl[4][2];
#pragma unroll
            for (int mi = 0; mi < 4; mi++)
#pragma unroll
                for (int t = 0; t < 4; t++) {
                    ah[mi][t] = tf32r(afv[mi][t]);
                    al[mi][t] = tf32r(afv[mi][t] - ah[mi][t]);
                }
#pragma unroll
            for (int ni = 0; ni < 4; ni++)
#pragma unroll
                for (int t = 0; t < 2; t++) {
                    bh[ni][t] = tf32r(bfv[ni][t]);
                    bl[ni][t] = tf32r(bfv[ni][t] - bh[ni][t]);
                }
#pragma unroll
            for (int mi = 0; mi < 4; mi++)
#pragma unroll
                for (int ni = 0; ni < 4; ni++) {
#define MMA1(AA, BB) \
    asm volatile( \
        "mma.sync.aligned.m16n8k8.row.col.f32.tf32.tf32.f32 " \
        "{%0,%1,%2,%3}, {%4,%5,%6,%7}, {%8,%9}, {%0,%1,%2,%3};" \
        : "+f"(acc[mi][ni][0]), "+f"(acc[mi][ni][1]), \
          "+f"(acc[mi][ni][2]), "+f"(acc[mi][ni][3]) \
        : "r"(__float_as_uint(AA[mi][0])), "r"(__float_as_uint(AA[mi][1])), \
          "r"(__float_as_uint(AA[mi][2])), "r"(__float_as_uint(AA[mi][3])), \
          "r"(__float_as_uint(BB[ni][0])), "r"(__float_as_uint(BB[ni][1])))
                    MMA1(al, bh);
                    MMA1(ah, bl);
                    MMA1(ah, bh);
#undef MMA1
                }
        }
        __syncthreads();
    }

#pragma unroll
    for (int mi = 0; mi < 4; mi++) {
        int r0 = row0 + wr * 64 + mi * 16 + g;
#pragma unroll
        for (int ni = 0; ni < 4; ni++) {
            int col = col0 + wc * 32 + ni * 8 + q * 2;
            float b0 = bias[col], b1 = bias[col + 1];
            float* p0 = C + (size_t)r0 * Nd + col;
            float* p1 = p0 + (size_t)8 * Nd;
            *(float2*)p0 = make_float2(acc[mi][ni][0] + b0, acc[mi][ni][1] + b1);
            *(float2*)p1 = make_float2(acc[mi][ni][2] + b0, acc[mi][ni][3] + b1);
        }
    }
}

// ---------------- attention dot products ----------------
template <typename T>
__global__ void k_att(const T* __restrict__ H, const float* __restrict__ av,
                      const float* __restrict__ dv, float* asum, float* dsum,
                      int heads) {
    int n = blockIdx.x;
    int w = threadIdx.x >> 5, lane = threadIdx.x & 31;
    const T* hp = H + ((size_t)n * heads + w) * CC;
    const float* ap = av + w * CC;
    const float* dp = dv + w * CC;
    float s1 = 0.f, s2 = 0.f;
    for (int c = lane; c < CC; c += 32) {
        float v = ldval(hp + c);
        s1 += v * ap[c];
        s2 += v * dp[c];
    }
#pragma unroll
    for (int o = 16; o; o >>= 1) {
        s1 += __shfl_xor_sync(0xffffffffu, s1, o);
        s2 += __shfl_xor_sync(0xffffffffu, s2, o);
    }
    if (lane == 0) {
        asum[n * heads + w] = s1;
        dsum[n * heads + w] = s2;
    }
}

// ---------------- fused layer-1 aggregation (fp16 in/out) ------------------
#define CH1 64
__global__ __launch_bounds__(256)
void k_agg1(const __half* __restrict__ H, const float* __restrict__ asrc,
            const float* __restrict__ adst, const float* __restrict__ bias,
            __half* __restrict__ out) {
    int d = blockIdx.x;
    int tid = threadIdx.x, wid = tid >> 5, lane = tid & 31;
    int beg = g_rptr[d], end = g_rptr[d + 1];
    __shared__ float s_m[H1H], s_den[H1H];
    __shared__ float s_coef[CH1 * H1H];
    __shared__ int s_src[CH1];

    {
        int h = wid;
        float adh = adst[d * H1H + h];
        float mx = -1e30f;
        for (int i = beg + lane; i < end; i += 32) {
            float v = asrc[g_csrc[i] * H1H + h] + adh;
            v = (v > 0.f) ? v : NEG_SLOPE * v;
            mx = fmaxf(mx, v);
        }
#pragma unroll
        for (int o = 16; o; o >>= 1) mx = fmaxf(mx, __shfl_xor_sync(~0u, mx, o));
        float sum = 0.f;
        for (int i = beg + lane; i < end; i += 32) {
            float v = asrc[g_csrc[i] * H1H + h] + adh;
            v = (v > 0.f) ? v : NEG_SLOPE * v;
            sum += expf(v - mx);
        }
#pragma unroll
        for (int o = 16; o; o >>= 1) sum += __shfl_xor_sync(~0u, sum, o);
        if (lane == 0) { s_m[h] = mx; s_den[h] = sum + 1e-16f; }
    }
    __syncthreads();

    int hk[24];
#pragma unroll
    for (int k = 0; k < 24; k++) hk[k] = (tid + k * 256) / CC;
    float acc[24];
#pragma unroll
    for (int k = 0; k < 24; k++) acc[k] = 0.f;

    for (int cb = beg; cb < end; cb += CH1) {
        int ch = min(CH1, end - cb);
        for (int i = tid; i < ch * H1H; i += 256) {
            int e = i >> 3, h = i & 7;
            int s = g_csrc[cb + e];
            float v = asrc[s * H1H + h] + adst[d * H1H + h];
            v = (v > 0.f) ? v : NEG_SLOPE * v;
            s_coef[i] = expf(v - s_m[h]) / s_den[h];
            if (h == 0) s_src[e] = s;
        }
        __syncthreads();
        for (int e = 0; e < ch; e++) {
            const __half* hp = H + (size_t)s_src[e] * F1;
            const float* cf = &s_coef[e * H1H];
#pragma unroll
            for (int k = 0; k < 24; k++)
                acc[k] += cf[hk[k]] * __half2float(hp[tid + k * 256]);
        }
        __syncthreads();
    }
#pragma unroll
    for (int k = 0; k < 24; k++) {
        int c = tid + k * 256;
        float v = acc[k] + bias[c];
        v = (v > 0.f) ? v : expm1f(v);
        out[(size_t)d * F1 + c] = __float2half(v);
    }
}

// ---------------- fused layer-2 aggregation (fp32) ----------------
#define CH2 128
__global__ __launch_bounds__(256)
void k_agg2(const float* __restrict__ H, const float* __restrict__ asrc,
            const float* __restrict__ adst, float* __restrict__ out) {
    int d = blockIdx.x;
    int tid = threadIdx.x, wid = tid >> 5, lane = tid & 31;
    int beg = g_rptr[d], end = g_rptr[d + 1];
    __shared__ float s_m, s_den;
    __shared__ float s_coef[CH2];
    __shared__ int s_src[CH2];

    if (wid == 0) {
        float adh = adst[d];
        float mx = -1e30f;
        for (int i = beg + lane; i < end; i += 32) {
            float v = asrc[g_csrc[i]] + adh;
            v = (v > 0.f) ? v : NEG_SLOPE * v;
            mx = fmaxf(mx, v);
        }
#pragma unroll
        for (int o = 16; o; o >>= 1) mx = fmaxf(mx, __shfl_xor_sync(~0u, mx, o));
        float sum = 0.f;
        for (int i = beg + lane; i < end; i += 32) {
            float v = asrc[g_csrc[i]] + adh;
            v = (v > 0.f) ? v : NEG_SLOPE * v;
            sum += expf(v - mx);
        }
#pragma unroll
        for (int o = 16; o; o >>= 1) sum += __shfl_xor_sync(~0u, sum, o);
        if (lane == 0) { s_m = mx; s_den = sum + 1e-16f; }
    }
    __syncthreads();

    float acc[3] = {0.f, 0.f, 0.f};
    for (int cb = beg; cb < end; cb += CH2) {
        int ch = min(CH2, end - cb);
        for (int i = tid; i < ch; i += 256) {
            int s = g_csrc[cb + i];
            float v = asrc[s] + adst[d];
            v = (v > 0.f) ? v : NEG_SLOPE * v;
            s_coef[i] = expf(v - s_m) / s_den;
            s_src[i] = s;
        }
        __syncthreads();
        for (int e = 0; e < ch; e++) {
            const float* hp = H + (size_t)s_src[e] * CC;
            float cf = s_coef[e];
#pragma unroll
            for (int k = 0; k < 3; k++)
                acc[k] += cf * hp[tid + k * 256];
        }
        __syncthreads();
    }
#pragma unroll
    for (int k = 0; k < 3; k++)
        out[(size_t)d * CC + tid + k * 256] = acc[k];
}

// ---------------- gather + concat (adds b2) ----------------
__global__ void k_cat(const float* __restrict__ out2, const float* __restrict__ b2,
                      const float* __restrict__ x) {
    int i = blockIdx.x * blockDim.x + threadIdx.x;
    if (i >= MM * CC) return;
    int m = i / CC, c = i - m * CC;
    int idx = g_midx[m];
    g_cat[(size_t)m * (2 * CC) + c] = out2[(size_t)idx * CC + c] + b2[c];
    g_cat[(size_t)m * (2 * CC) + CC + c] = x[(size_t)idx * DD + c];
}

// ---------------- classifier ----------------
__global__ void k_cls(const float* __restrict__ fc, const float* __restrict__ w,
                      const float* __restrict__ b, float* __restrict__ out) {
    int m = blockIdx.x, t = threadIdx.x;
    float s0 = 0.f, s1 = 0.f;
    for (int c = t; c < CC; c += 256) {
        float v = fc[(size_t)m * CC + c];
        s0 += v * w[c * 2 + 0];
        s1 += v * w[c * 2 + 1];
    }
    __shared__ float r0[256], r1[256];
    r0[t] = s0; r1[t] = s1;
    __syncthreads();
    for (int o = 128; o; o >>= 1) {
        if (t < o) { r0[t] += r0[t + o]; r1[t] += r1[t + o]; }
        __syncthreads();
    }
    if (t == 0) {
        out[m * 2 + 0] = r0[0] + b[0];
        out[m * 2 + 1] = r1[0] + b[1];
    }
}

// ---------------- launch ----------------
extern "C" void kernel_launch(void* const* d_in, const int* in_sizes, int n_in,
                              void* d_out, int out_size) {
    (void)in_sizes; (void)n_in; (void)out_size;
    const float* x   = (const float*)d_in[0];
    const void*  eix = d_in[1];
    const void*  mix = d_in[2];
    const float* W1  = (const float*)d_in[3];
    const float* as1 = (const float*)d_in[4];
    const float* ad1 = (const float*)d_in[5];
    const float* b1  = (const float*)d_in[6];
    const float* W2  = (const float*)d_in[7];
    const float* as2 = (const float*)d_in[8];
    const float* ad2 = (const float*)d_in[9];
    const float* b2  = (const float*)d_in[10];
    const float* fcw = (const float*)d_in[11];
    const float* fcb = (const float*)d_in[12];
    const float* clw = (const float*)d_in[13];
    const float* clb = (const float*)d_in[14];
    float* out = (float*)d_out;

    void *pH1h, *pOut1h, *pH2, *pOut2, *pXh, *pAs1, *pAd1, *pAs2, *pAd2;
    void *pCat, *pFc, *pW1T, *pW2T, *pFcwT, *pCnt;
    cudaGetSymbolAddress(&pH1h, g_H1h);
    cudaGetSymbolAddress(&pOut1h, g_out1h);
    cudaGetSymbolAddress(&pH2, g_H2);
    cudaGetSymbolAddress(&pOut2, g_out2);
    cudaGetSymbolAddress(&pXh, g_xh);
    cudaGetSymbolAddress(&pAs1, g_asrc1);
    cudaGetSymbolAddress(&pAd1, g_adst1);
    cudaGetSymbolAddress(&pAs2, g_asrc2);
    cudaGetSymbolAddress(&pAd2, g_adst2);
    cudaGetSymbolAddress(&pCat, g_cat);
    cudaGetSymbolAddress(&pFc, g_fc);
    cudaGetSymbolAddress(&pW1T, g_W1T);
    cudaGetSymbolAddress(&pW2T, g_W2T);
    cudaGetSymbolAddress(&pFcwT, g_fcwT);
    cudaGetSymbolAddress(&pCnt, g_cnt);

    const int TF_SMEM = STG * 2 * TILE_F * 4;    // 110592 B
    const int H_SMEM  = STG * 2 * HTILE * 2;     // 61440 B
    cudaFuncSetAttribute(mma_gemm_p3, cudaFuncAttributeMaxDynamicSharedMemorySize,
                         TF_SMEM);
    cudaFuncSetAttribute(hgemm<__half>, cudaFuncAttributeMaxDynamicSharedMemorySize,
                         H_SMEM);
    cudaFuncSetAttribute(hgemm<float>, cudaFuncAttributeMaxDynamicSharedMemorySize,
                         H_SMEM);

    cudaMemsetAsync(pCnt, 0, NN * sizeof(int));
    k_detect<<<1, 32>>>((const unsigned*)eix, (const unsigned*)mix);
    k_prep<<<(EP + 255) / 256, 256>>>(eix, mix);
    k_count<<<(EP + 255) / 256, 256>>>();
    k_scan<<<1, 1024>>>();
    k_fill<<<(EP + 255) / 256, 256>>>();

    k_cvt_h<<<(int)(((size_t)NN * DD + 255) / 256), 256>>>(x, (__half*)pXh,
                                                           (size_t)NN * DD);
    k_transpose<__half><<<dim3(F1 / 32, DD / 32), dim3(32, 8)>>>(
        W1, (__half*)pW1T, DD, F1);
    k_transpose<__half><<<dim3(CC / 32, F1 / 32), dim3(32, 8)>>>(
        W2, (__half*)pW2T, F1, CC);
    k_transpose<float><<<dim3(CC / 32, (2 * CC) / 32), dim3(32, 8)>>>(
        fcw, (float*)pFcwT, 2 * CC, CC);

    // ---- layer 1 ----
    hgemm<__half><<<dim3(F1 / BN, NN / BM), GT, H_SMEM>>>(
        (const __half*)pXh, (const __half*)pW1T, (__half*)pH1h, F1, DD);
    k_att<__half><<<NN, 32 * H1H>>>((const __half*)pH1h, as1, ad1,
                                    (float*)pAs1, (float*)pAd1, H1H);
    k_agg1<<<NN, 256>>>((const __half*)pH1h, (const float*)pAs1, (const float*)pAd1,
                        b1, (__half*)pOut1h);

    // ---- layer 2 ----
    hgemm<float><<<dim3(CC / BN, NN / BM), GT, H_SMEM>>>(
        (const __half*)pOut1h, (const __half*)pW2T, (float*)pH2, CC, F1);
    k_att<float><<<NN, 32>>>((const float*)pH2, as2, ad2,
                             (float*)pAs2, (float*)pAd2, 1);
    k_agg2<<<NN, 256>>>((const float*)pH2, (const float*)pAs2, (const float*)pAd2,
                        (float*)pOut2);

    // ---- head ----
    k_cat<<<(MM * CC + 255) / 256, 256>>>((const float*)pOut2, b2, x);
    mma_gemm_p3<<<dim3(CC / BN, MM / BM), GT, TF_SMEM>>>(
        (const float*)pCat, (const float*)pFcwT, (float*)pFc, CC, 2 * CC, fcb);
    k_cls<<<MM, 256>>>((const float*)pFc, clw, clb, out);
}